// round 6
// baseline (speedup 1.0000x reference)
#include <cuda_runtime.h>
#include <cstdint>
#include <math.h>

#define B_ 2
#define L_ 2048
#define E_ 1024
#define H_ 8
#define D_ 128

// Scratch (allocation-free rule: __device__ globals)
__device__ float g_Q[B_ * L_ * E_];
__device__ float g_K[B_ * L_ * E_];
__device__ float g_V[B_ * L_ * E_];
__device__ float g_ctx[B_ * L_ * E_];
// pre-split bf16 hi/lo operands (reused across the 4 sequential GEMMs)
__device__ uint16_t g_Ah[B_ * L_ * E_];
__device__ uint16_t g_Al[B_ * L_ * E_];
__device__ uint16_t g_Wh[E_ * E_];
__device__ uint16_t g_Wl[E_ * E_];

__constant__ int c_anchors[10] = {204, 409, 614, 781, 1023, 1265, 1432, 1637, 1842, 2047};

// ===========================================================================
// helpers
// ===========================================================================
__device__ __forceinline__ uint32_t smem_u32(const void* p) {
    uint32_t a;
    asm("{ .reg .u64 t; cvta.to.shared.u64 t, %1; cvt.u32.u64 %0, t; }" : "=r"(a) : "l"(p));
    return a;
}

// pack two f32 -> bf16x2 (x0 -> low half, x1 -> high half)
__device__ __forceinline__ uint32_t pack_bf16x2(float x0, float x1) {
    uint32_t r;
    asm("cvt.rn.bf16x2.f32 %0, %2, %1;" : "=r"(r) : "f"(x0), "f"(x1));
    return r;
}

__device__ __forceinline__ void ldsm4(uint32_t* r, uint32_t addr) {
    asm volatile("ldmatrix.sync.aligned.m8n8.x4.shared.b16 {%0,%1,%2,%3}, [%4];"
                 : "=r"(r[0]), "=r"(r[1]), "=r"(r[2]), "=r"(r[3]) : "r"(addr));
}

__device__ __forceinline__ void mma_bf16(float* d, const uint32_t* a, const uint32_t* b) {
    asm volatile(
        "mma.sync.aligned.m16n8k16.row.col.f32.bf16.bf16.f32 "
        "{%0,%1,%2,%3}, {%4,%5,%6,%7}, {%8,%9}, {%0,%1,%2,%3};"
        : "+f"(d[0]), "+f"(d[1]), "+f"(d[2]), "+f"(d[3])
        : "r"(a[0]), "r"(a[1]), "r"(a[2]), "r"(a[3]), "r"(b[0]), "r"(b[1]));
}

#define CP16(dst, src) \
    asm volatile("cp.async.cg.shared.global [%0], [%1], 16;" :: "r"(dst), "l"(src) : "memory")

// ===========================================================================
// Pre-split: fp32 -> bf16 hi + bf16 lo (lo = x - bf16(x), exact in fp32)
// ===========================================================================
__global__ __launch_bounds__(256)
void split_kernel(const float4* __restrict__ X, uint2* __restrict__ Xh,
                  uint2* __restrict__ Xl, int n4) {
    int i = blockIdx.x * blockDim.x + threadIdx.x;
    if (i >= n4) return;
    float4 v = X[i];
    uint32_t h0 = pack_bf16x2(v.x, v.y);
    uint32_t h1 = pack_bf16x2(v.z, v.w);
    float l0 = v.x - __uint_as_float(h0 << 16);
    float l1 = v.y - __uint_as_float(h0 & 0xFFFF0000u);
    float l2 = v.z - __uint_as_float(h1 << 16);
    float l3 = v.w - __uint_as_float(h1 & 0xFFFF0000u);
    Xh[i] = make_uint2(h0, h1);
    Xl[i] = make_uint2(pack_bf16x2(l0, l1), pack_bf16x2(l2, l3));
}

// ===========================================================================
// Tensor-core GEMM v2 (pre-split bf16 inputs, cp.async double buffer):
//   C[4096,1024] = A @ W^T + bias,   fp32 result = AhWh + AhWl + AlWh
// CTA 128x128, 8 warps (2m x 4n), warp tile 64x32, BK=32, 2-stage pipeline.
// SMEM rows padded to 80 B (64 B data + 16 pad) -> conflict-free ldmatrix.
// ===========================================================================
#define LDA 80
#define ARR_B (128 * LDA)        // 10240 per array
#define AH_OFF 0
#define AL_OFF ARR_B
#define WH_OFF (2 * ARR_B)
#define WL_OFF (3 * ARR_B)
#define STAGE_B (4 * ARR_B)      // 40960
#define GSMEM (2 * STAGE_B)      // 81920

__device__ __forceinline__ void stage_load(
    uint32_t sb, int st, int kt, int tid,
    const uint16_t* __restrict__ AgH, const uint16_t* __restrict__ AgL,
    const uint16_t* __restrict__ WgH, const uint16_t* __restrict__ WgL)
{
    int srow = tid >> 1;                    // 0..127
    int half = tid & 1;                     // 0/1 -> bytes [0,32) / [32,64)
    uint32_t dst = sb + (uint32_t)st * STAGE_B + (uint32_t)srow * LDA + half * 32;
    size_t go = (size_t)srow * 1024 + kt * 32 + half * 16;
    const uint16_t* s0 = AgH + go;
    CP16(dst + AH_OFF, s0); CP16(dst + AH_OFF + 16, s0 + 8);
    const uint16_t* s1 = AgL + go;
    CP16(dst + AL_OFF, s1); CP16(dst + AL_OFF + 16, s1 + 8);
    const uint16_t* s2 = WgH + go;
    CP16(dst + WH_OFF, s2); CP16(dst + WH_OFF + 16, s2 + 8);
    const uint16_t* s3 = WgL + go;
    CP16(dst + WL_OFF, s3); CP16(dst + WL_OFF + 16, s3 + 8);
    asm volatile("cp.async.commit_group;" ::: "memory");
}

__global__ __launch_bounds__(256, 2)
void gemm_tc_kernel(const uint16_t* __restrict__ Ah, const uint16_t* __restrict__ Al,
                    const uint16_t* __restrict__ Wh, const uint16_t* __restrict__ Wl,
                    const float* __restrict__ bias, float* __restrict__ C) {
    extern __shared__ __align__(16) uint8_t sm[];
    uint32_t sb = smem_u32(sm);

    int tid = threadIdx.x;
    int lane = tid & 31;
    int wid = tid >> 5;
    int warpM = wid >> 2;       // 0..1  -> m offset *64
    int warpN = wid & 3;        // 0..3  -> n offset *32

    const uint16_t* AgH = Ah + (size_t)blockIdx.y * 128 * 1024;
    const uint16_t* AgL = Al + (size_t)blockIdx.y * 128 * 1024;
    const uint16_t* WgH = Wh + (size_t)blockIdx.x * 128 * 1024;
    const uint16_t* WgL = Wl + (size_t)blockIdx.x * 128 * 1024;

    float acc[4][4][4];
#pragma unroll
    for (int f = 0; f < 4; ++f)
#pragma unroll
        for (int g = 0; g < 4; ++g)
#pragma unroll
            for (int r = 0; r < 4; ++r) acc[f][g][r] = 0.0f;

    // ldmatrix source addresses (within a stage; add stage base at use)
    uint32_t aRow = (uint32_t)(warpM * 64) + (lane & 15);
    uint32_t aAddrBase = aRow * LDA + ((lane >> 4) << 4);
    uint32_t bRow = (uint32_t)(warpN * 32) + (lane & 7) + ((lane >> 4) << 3);
    uint32_t bAddrBase = bRow * LDA + (((lane >> 3) & 1) << 4);

    stage_load(sb, 0, 0, tid, AgH, AgL, WgH, WgL);

    for (int kt = 0; kt < 32; ++kt) {
        if (kt < 31) {
            stage_load(sb, (kt + 1) & 1, kt + 1, tid, AgH, AgL, WgH, WgL);
            asm volatile("cp.async.wait_group 1;" ::: "memory");
        } else {
            asm volatile("cp.async.wait_group 0;" ::: "memory");
        }
        __syncthreads();

        uint32_t stg = sb + (uint32_t)(kt & 1) * STAGE_B;
#pragma unroll
        for (int ks = 0; ks < 2; ++ks) {
            uint32_t koff = ks * 32;
            uint32_t bH[2][4], bL[2][4];
            ldsm4(bH[0], stg + WH_OFF + bAddrBase + koff);
            ldsm4(bH[1], stg + WH_OFF + bAddrBase + 16 * LDA + koff);
            ldsm4(bL[0], stg + WL_OFF + bAddrBase + koff);
            ldsm4(bL[1], stg + WL_OFF + bAddrBase + 16 * LDA + koff);
#pragma unroll
            for (int f = 0; f < 4; ++f) {
                uint32_t aH[4], aL[4];
                ldsm4(aH, stg + AH_OFF + aAddrBase + (uint32_t)(f * 16) * LDA + koff);
                ldsm4(aL, stg + AL_OFF + aAddrBase + (uint32_t)(f * 16) * LDA + koff);
#pragma unroll
                for (int g = 0; g < 4; ++g) {
                    const uint32_t* bh = &bH[g >> 1][(g & 1) * 2];
                    const uint32_t* bl = &bL[g >> 1][(g & 1) * 2];
                    mma_bf16(acc[f][g], aH, bh);
                    mma_bf16(acc[f][g], aL, bh);
                    mma_bf16(acc[f][g], aH, bl);
                }
            }
        }
        __syncthreads();
    }

    // epilogue: acc[f][g] is m16n8: d0,d1 @ (row=lane>>2, col=2*(lane&3)), d2,d3 @ row+8
    int crow = blockIdx.y * 128 + warpM * 64 + (lane >> 2);
    int ccol0 = blockIdx.x * 128 + warpN * 32 + (lane & 3) * 2;
#pragma unroll
    for (int g = 0; g < 4; ++g) {
        int c = ccol0 + g * 8;
        float2 bv = *(const float2*)(bias + c);
#pragma unroll
        for (int f = 0; f < 4; ++f) {
            int r = crow + f * 16;
            float2 o0 = make_float2(acc[f][g][0] + bv.x, acc[f][g][1] + bv.y);
            float2 o1 = make_float2(acc[f][g][2] + bv.x, acc[f][g][3] + bv.y);
            *(float2*)(C + (size_t)r * 1024 + c) = o0;
            *(float2*)(C + (size_t)(r + 8) * 1024 + c) = o1;
        }
    }
}

// ===========================================================================
// Sparse attention (R3 version — near L1 floor, unchanged)
// ===========================================================================
__device__ __forceinline__ void visit4(
    const float* __restrict__ Kb, const float* __restrict__ Vb,
    int j0, int j1, int j2, int j3, int count,
    float4 q, int lane, float& s, float4& o)
{
    const float4* k0 = (const float4*)(Kb + (size_t)j0 * E_);
    const float4* k1 = (const float4*)(Kb + (size_t)j1 * E_);
    const float4* k2 = (const float4*)(Kb + (size_t)j2 * E_);
    const float4* k3 = (const float4*)(Kb + (size_t)j3 * E_);
    float4 ka = k0[lane];
    float4 kb = k1[lane];
    float4 kc = k2[lane];
    float4 kd = k3[lane];
    float d0 = q.x * ka.x + q.y * ka.y + q.z * ka.z + q.w * ka.w;
    float d1 = q.x * kb.x + q.y * kb.y + q.z * kb.z + q.w * kb.w;
    float d2 = q.x * kc.x + q.y * kc.y + q.z * kc.z + q.w * kc.w;
    float d3 = q.x * kd.x + q.y * kd.y + q.z * kd.z + q.w * kd.w;
#pragma unroll
    for (int off = 16; off > 0; off >>= 1) {
        d0 += __shfl_xor_sync(0xffffffffu, d0, off);
        d1 += __shfl_xor_sync(0xffffffffu, d1, off);
        d2 += __shfl_xor_sync(0xffffffffu, d2, off);
        d3 += __shfl_xor_sync(0xffffffffu, d3, off);
    }
    const float S = 0.08838834764831845f;  // 1/sqrt(128)
    float p0 = __expf(d0 * S - 8.0f);
    float p1 = __expf(d1 * S - 8.0f);
    float p2 = __expf(d2 * S - 8.0f);
    float p3 = __expf(d3 * S - 8.0f);
    if (count < 2) p1 = 0.0f;
    if (count < 3) p2 = 0.0f;
    if (count < 4) p3 = 0.0f;
    s += (p0 + p1) + (p2 + p3);
    const float4* v0 = (const float4*)(Vb + (size_t)j0 * E_);
    const float4* v1 = (const float4*)(Vb + (size_t)j1 * E_);
    const float4* v2 = (const float4*)(Vb + (size_t)j2 * E_);
    const float4* v3 = (const float4*)(Vb + (size_t)j3 * E_);
    float4 va = v0[lane];
    float4 vb = v1[lane];
    float4 vc = v2[lane];
    float4 vd = v3[lane];
    o.x += p0 * va.x + p1 * vb.x + p2 * vc.x + p3 * vd.x;
    o.y += p0 * va.y + p1 * vb.y + p2 * vc.y + p3 * vd.y;
    o.z += p0 * va.z + p1 * vb.z + p2 * vc.z + p3 * vd.z;
    o.w += p0 * va.w + p1 * vb.w + p2 * vc.w + p3 * vd.w;
}

__device__ __forceinline__ void visit_range(
    const float* __restrict__ Kb, const float* __restrict__ Vb,
    int lo, int hi, int st,
    float4 q, int lane, float& s, float4& o)
{
    for (int j = lo; j <= hi; j += 4 * st) {
        int rem = (hi - j) / st + 1;
        int cnt = rem < 4 ? rem : 4;
        int jb = (cnt > 1) ? j + st     : j;
        int jc = (cnt > 2) ? j + 2 * st : j;
        int jd = (cnt > 3) ? j + 3 * st : j;
        visit4(Kb, Vb, j, jb, jc, jd, cnt, q, lane, s, o);
    }
}

__global__ __launch_bounds__(256)
void sparse_attn_kernel() {
    int gw   = (blockIdx.x * blockDim.x + threadIdx.x) >> 5;
    int lane = threadIdx.x & 31;
    int i  = gw & (L_ - 1);
    int bh = gw >> 11;
    int h  = bh & (H_ - 1);
    int b  = bh >> 3;

    const float* Qp = g_Q + ((size_t)(b * L_ + i)) * E_ + h * D_;
    float4 q = ((const float4*)Qp)[lane];
    const float* Kb = g_K + (size_t)b * L_ * E_ + h * D_;
    const float* Vb = g_V + (size_t)b * L_ * E_ + h * D_;

    float s = 0.0f;
    float4 o = make_float4(0.0f, 0.0f, 0.0f, 0.0f);

    int cl = (h == 0) ? 0 : (h <= 2) ? 3 : (h <= 5) ? 1 : 2;

    if (cl == 0) {
        int lo = i - 8; if (lo < 0) lo = 0;
        visit_range(Kb, Vb, lo, i, 1, q, lane, s, o);
    } else if (cl == 3) {
        int lo = i - 16; if (lo < 0) lo = 0;
        visit_range(Kb, Vb, lo, i, 1, q, lane, s, o);
    } else if (cl == 1) {
        int lo = i - 32; if (lo < 0) lo = 0;
        if (lo > 0)
            visit_range(Kb, Vb, 0, lo - 1 - ((lo - 1) & 7), 8, q, lane, s, o);
        visit_range(Kb, Vb, lo, i, 1, q, lane, s, o);
    } else {
        visit_range(Kb, Vb, 0, i - (i & 15), 16, q, lane, s, o);
        int cnt = 0;
#pragma unroll
        for (int t = 0; t < 10; ++t)
            if (c_anchors[t] <= i) ++cnt;
        for (int base = 0; base < cnt; base += 4) {
            int c = cnt - base; if (c > 4) c = 4;
            int a0 = c_anchors[base];
            int a1 = c_anchors[(c > 1) ? base + 1 : base];
            int a2 = c_anchors[(c > 2) ? base + 2 : base];
            int a3 = c_anchors[(c > 3) ? base + 3 : base];
            visit4(Kb, Vb, a0, a1, a2, a3, c, q, lane, s, o);
        }
    }

    float inv = 1.0f / s;
    float* op = g_ctx + ((size_t)(b * L_ + i)) * E_ + h * D_;
    float4 r = make_float4(o.x * inv, o.y * inv, o.z * inv, o.w * inv);
    ((float4*)op)[lane] = r;
}

// ---------------------------------------------------------------------------
extern "C" void kernel_launch(void* const* d_in, const int* in_sizes, int n_in,
                              void* d_out, int out_size) {
    const float* query = (const float*)d_in[0];
    const float* key_  = (const float*)d_in[1];
    const float* value = (const float*)d_in[2];
    const float* Wq = (const float*)d_in[3];
    const float* bq = (const float*)d_in[4];
    const float* Wk = (const float*)d_in[5];
    const float* bk = (const float*)d_in[6];
    const float* Wv = (const float*)d_in[7];
    const float* bv = (const float*)d_in[8];
    const float* Wo = (const float*)d_in[9];
    const float* bo = (const float*)d_in[10];
    float* out = (float*)d_out;

    float *Qd, *Kd, *Vd, *Cd;
    cudaGetSymbolAddress((void**)&Qd, g_Q);
    cudaGetSymbolAddress((void**)&Kd, g_K);
    cudaGetSymbolAddress((void**)&Vd, g_V);
    cudaGetSymbolAddress((void**)&Cd, g_ctx);
    uint16_t *Ah, *Al, *Whd, *Wld;
    cudaGetSymbolAddress((void**)&Ah, g_Ah);
    cudaGetSymbolAddress((void**)&Al, g_Al);
    cudaGetSymbolAddress((void**)&Whd, g_Wh);
    cudaGetSymbolAddress((void**)&Wld, g_Wl);

    cudaFuncSetAttribute(gemm_tc_kernel,
                         cudaFuncAttributeMaxDynamicSharedMemorySize, GSMEM);

    dim3 ggrid(E_ / 128, (B_ * L_) / 128);   // 8 x 32 = 256 CTAs
    const int nA4 = B_ * L_ * E_ / 4;        // 1M float4
    const int nW4 = E_ * E_ / 4;             // 256K float4

    // Q = query @ Wq^T + bq
    split_kernel<<<nA4 / 256, 256>>>((const float4*)query, (uint2*)Ah, (uint2*)Al, nA4);
    split_kernel<<<nW4 / 256, 256>>>((const float4*)Wq, (uint2*)Whd, (uint2*)Wld, nW4);
    gemm_tc_kernel<<<ggrid, 256, GSMEM>>>(Ah, Al, Whd, Wld, bq, Qd);

    // K
    split_kernel<<<nA4 / 256, 256>>>((const float4*)key_, (uint2*)Ah, (uint2*)Al, nA4);
    split_kernel<<<nW4 / 256, 256>>>((const float4*)Wk, (uint2*)Whd, (uint2*)Wld, nW4);
    gemm_tc_kernel<<<ggrid, 256, GSMEM>>>(Ah, Al, Whd, Wld, bk, Kd);

    // V
    split_kernel<<<nA4 / 256, 256>>>((const float4*)value, (uint2*)Ah, (uint2*)Al, nA4);
    split_kernel<<<nW4 / 256, 256>>>((const float4*)Wv, (uint2*)Whd, (uint2*)Wld, nW4);
    gemm_tc_kernel<<<ggrid, 256, GSMEM>>>(Ah, Al, Whd, Wld, bv, Vd);

    // attention
    int total_warps = B_ * H_ * L_;                 // 32768
    sparse_attn_kernel<<<total_warps * 32 / 256, 256>>>();

    // out = ctx @ Wo^T + bo
    split_kernel<<<nA4 / 256, 256>>>((const float4*)Cd, (uint2*)Ah, (uint2*)Al, nA4);
    split_kernel<<<nW4 / 256, 256>>>((const float4*)Wo, (uint2*)Whd, (uint2*)Wld, nW4);
    gemm_tc_kernel<<<ggrid, 256, GSMEM>>>(Ah, Al, Whd, Wld, bo, out);
}

// round 7
// speedup vs baseline: 1.0662x; 1.0662x over previous
#include <cuda_runtime.h>
#include <cuda_fp16.h>
#include <cstdint>
#include <math.h>

#define B_ 2
#define L_ 2048
#define E_ 1024
#define H_ 8
#define D_ 128

// Scratch (allocation-free rule: __device__ globals)
__device__ float  g_Q[B_ * L_ * E_];
__device__ __half g_Kh[B_ * L_ * E_];
__device__ __half g_Vh[B_ * L_ * E_];
__device__ float  g_ctx[B_ * L_ * E_];

__constant__ int c_anchors[10] = {204, 409, 614, 781, 1023, 1265, 1432, 1637, 1842, 2047};

// ===========================================================================
// helpers
// ===========================================================================
__device__ __forceinline__ uint32_t smem_u32(const void* p) {
    uint32_t a;
    asm("{ .reg .u64 t; cvta.to.shared.u64 t, %1; cvt.u32.u64 %0, t; }" : "=r"(a) : "l"(p));
    return a;
}

// pack two f32 -> bf16x2 (x0 -> low half, x1 -> high half)
__device__ __forceinline__ uint32_t pack_bf16x2(float x0, float x1) {
    uint32_t r;
    asm("cvt.rn.bf16x2.f32 %0, %2, %1;" : "=r"(r) : "f"(x0), "f"(x1));
    return r;
}

__device__ __forceinline__ void ldsm4(uint32_t* r, uint32_t addr) {
    asm volatile("ldmatrix.sync.aligned.m8n8.x4.shared.b16 {%0,%1,%2,%3}, [%4];"
                 : "=r"(r[0]), "=r"(r[1]), "=r"(r[2]), "=r"(r[3]) : "r"(addr));
}

__device__ __forceinline__ void mma_bf16(float* d, const uint32_t* a, const uint32_t* b) {
    asm volatile(
        "mma.sync.aligned.m16n8k16.row.col.f32.bf16.bf16.f32 "
        "{%0,%1,%2,%3}, {%4,%5,%6,%7}, {%8,%9}, {%0,%1,%2,%3};"
        : "+f"(d[0]), "+f"(d[1]), "+f"(d[2]), "+f"(d[3])
        : "r"(a[0]), "r"(a[1]), "r"(a[2]), "r"(a[3]), "r"(b[0]), "r"(b[1]));
}

// ===========================================================================
// Tensor-core GEMM (mma.sync HMMA, split-bf16 hi/lo inline, fp32 accum):
//   C[4096,1024] = A[4096,1024] @ W[1024,1024]^T + bias
// CTA 128x128, 8 warps (2m x 4n), warp tile 64x32, BK=32.
// HALF_OUT: epilogue writes __half (for K/V consumed by attention).
// ===========================================================================
#define LDA 80
#define T_BYTES (128 * LDA)    // 10240 per array
#define AH_OFF 0
#define AL_OFF (T_BYTES)
#define WH_OFF (2 * T_BYTES)
#define WL_OFF (3 * T_BYTES)

template <bool HALF_OUT>
__global__ __launch_bounds__(256, 1)
void gemm_tc_kernel(const float* __restrict__ A, const float* __restrict__ W,
                    const float* __restrict__ bias, void* __restrict__ Cout) {
    __shared__ __align__(16) uint8_t sm[4 * T_BYTES];   // 40960 B
    uint32_t sb = smem_u32(sm);

    int tid = threadIdx.x;
    int lane = tid & 31;
    int wid = tid >> 5;
    int warpM = wid >> 2;       // 0..1  -> m offset *64
    int warpN = wid & 3;        // 0..3  -> n offset *32

    const float* Ag = A + (size_t)blockIdx.y * 128 * 1024;
    const float* Wg = W + (size_t)blockIdx.x * 128 * 1024;

    int r0 = tid >> 3;          // 0..31, rows r0 + i*32
    int c4 = tid & 7;           // float4 index within 32-col row

    // prefetch chunk 0
    float4 pa[4], pw[4];
#pragma unroll
    for (int i = 0; i < 4; ++i) {
        pa[i] = *(const float4*)(Ag + (size_t)(r0 + i * 32) * 1024 + c4 * 4);
        pw[i] = *(const float4*)(Wg + (size_t)(r0 + i * 32) * 1024 + c4 * 4);
    }

    float acc[4][4][4];
#pragma unroll
    for (int f = 0; f < 4; ++f)
#pragma unroll
        for (int g = 0; g < 4; ++g)
#pragma unroll
            for (int r = 0; r < 4; ++r) acc[f][g][r] = 0.0f;

    uint32_t aRow = (uint32_t)(warpM * 64) + (lane & 15);
    uint32_t aAddrBase = aRow * LDA + ((lane >> 4) << 4);
    uint32_t bRow = (uint32_t)(warpN * 32) + (lane & 7) + ((lane >> 4) << 3);
    uint32_t bAddrBase = bRow * LDA + (((lane >> 3) & 1) << 4);

    for (int kt = 0; kt < 32; ++kt) {
#pragma unroll
        for (int i = 0; i < 4; ++i) {
            uint32_t so = (uint32_t)(r0 + i * 32) * LDA + c4 * 8;
            float4 v = pa[i];
            uint32_t h0 = pack_bf16x2(v.x, v.y);
            uint32_t h1 = pack_bf16x2(v.z, v.w);
            float l0 = v.x - __uint_as_float(h0 << 16);
            float l1 = v.y - __uint_as_float(h0 & 0xFFFF0000u);
            float l2 = v.z - __uint_as_float(h1 << 16);
            float l3 = v.w - __uint_as_float(h1 & 0xFFFF0000u);
            *(uint2*)(sm + AH_OFF + so) = make_uint2(h0, h1);
            *(uint2*)(sm + AL_OFF + so) = make_uint2(pack_bf16x2(l0, l1), pack_bf16x2(l2, l3));
            v = pw[i];
            h0 = pack_bf16x2(v.x, v.y);
            h1 = pack_bf16x2(v.z, v.w);
            l0 = v.x - __uint_as_float(h0 << 16);
            l1 = v.y - __uint_as_float(h0 & 0xFFFF0000u);
            l2 = v.z - __uint_as_float(h1 << 16);
            l3 = v.w - __uint_as_float(h1 & 0xFFFF0000u);
            *(uint2*)(sm + WH_OFF + so) = make_uint2(h0, h1);
            *(uint2*)(sm + WL_OFF + so) = make_uint2(pack_bf16x2(l0, l1), pack_bf16x2(l2, l3));
        }
        __syncthreads();

        if (kt < 31) {
            int k0 = (kt + 1) * 32;
#pragma unroll
            for (int i = 0; i < 4; ++i) {
                pa[i] = *(const float4*)(Ag + (size_t)(r0 + i * 32) * 1024 + k0 + c4 * 4);
                pw[i] = *(const float4*)(Wg + (size_t)(r0 + i * 32) * 1024 + k0 + c4 * 4);
            }
        }

#pragma unroll
        for (int ks = 0; ks < 2; ++ks) {
            uint32_t koff = ks * 32;
            uint32_t bH[2][4], bL[2][4];
            ldsm4(bH[0], sb + WH_OFF + bAddrBase + koff);
            ldsm4(bH[1], sb + WH_OFF + bAddrBase + 16 * LDA + koff);
            ldsm4(bL[0], sb + WL_OFF + bAddrBase + koff);
            ldsm4(bL[1], sb + WL_OFF + bAddrBase + 16 * LDA + koff);
#pragma unroll
            for (int f = 0; f < 4; ++f) {
                uint32_t aH[4], aL[4];
                ldsm4(aH, sb + AH_OFF + aAddrBase + (uint32_t)(f * 16) * LDA + koff);
                ldsm4(aL, sb + AL_OFF + aAddrBase + (uint32_t)(f * 16) * LDA + koff);
#pragma unroll
                for (int g = 0; g < 4; ++g) {
                    const uint32_t* bh = &bH[g >> 1][(g & 1) * 2];
                    const uint32_t* bl = &bL[g >> 1][(g & 1) * 2];
                    mma_bf16(acc[f][g], aH, bh);
                    mma_bf16(acc[f][g], aL, bh);
                    mma_bf16(acc[f][g], aH, bl);
                }
            }
        }
        __syncthreads();
    }

    // epilogue
    int crow = blockIdx.y * 128 + warpM * 64 + (lane >> 2);
    int ccol0 = blockIdx.x * 128 + warpN * 32 + (lane & 3) * 2;
#pragma unroll
    for (int g = 0; g < 4; ++g) {
        int c = ccol0 + g * 8;
        float2 bv = *(const float2*)(bias + c);
#pragma unroll
        for (int f = 0; f < 4; ++f) {
            int r = crow + f * 16;
            float2 o0 = make_float2(acc[f][g][0] + bv.x, acc[f][g][1] + bv.y);
            float2 o1 = make_float2(acc[f][g][2] + bv.x, acc[f][g][3] + bv.y);
            if (HALF_OUT) {
                __half* Ch = (__half*)Cout;
                *(__half2*)(Ch + (size_t)r * 1024 + c) = __floats2half2_rn(o0.x, o0.y);
                *(__half2*)(Ch + (size_t)(r + 8) * 1024 + c) = __floats2half2_rn(o1.x, o1.y);
            } else {
                float* Cf = (float*)Cout;
                *(float2*)(Cf + (size_t)r * 1024 + c) = o0;
                *(float2*)(Cf + (size_t)(r + 8) * 1024 + c) = o1;
            }
        }
    }
}

// ===========================================================================
// Sparse attention v3: fp16 K/V (halved L1 traffic), fp32 q/softmax/accum.
// One warp per (b,h,i); 4 keys per step; no online max (p = exp(score-8)).
// ===========================================================================
__device__ __forceinline__ float dot_h(float4 q, uint2 r) {
    float2 a0 = __half22float2(*(__half2*)&r.x);
    float2 a1 = __half22float2(*(__half2*)&r.y);
    return q.x * a0.x + q.y * a0.y + q.z * a1.x + q.w * a1.y;
}

__device__ __forceinline__ void visit4(
    const __half* __restrict__ Kb, const __half* __restrict__ Vb,
    int j0, int j1, int j2, int j3, int count,
    float4 q, int lane, float& s, float4& o)
{
    uint2 ka = ((const uint2*)(Kb + (size_t)j0 * E_))[lane];
    uint2 kb = ((const uint2*)(Kb + (size_t)j1 * E_))[lane];
    uint2 kc = ((const uint2*)(Kb + (size_t)j2 * E_))[lane];
    uint2 kd = ((const uint2*)(Kb + (size_t)j3 * E_))[lane];
    float d0 = dot_h(q, ka);
    float d1 = dot_h(q, kb);
    float d2 = dot_h(q, kc);
    float d3 = dot_h(q, kd);
#pragma unroll
    for (int off = 16; off > 0; off >>= 1) {
        d0 += __shfl_xor_sync(0xffffffffu, d0, off);
        d1 += __shfl_xor_sync(0xffffffffu, d1, off);
        d2 += __shfl_xor_sync(0xffffffffu, d2, off);
        d3 += __shfl_xor_sync(0xffffffffu, d3, off);
    }
    const float S = 0.08838834764831845f;  // 1/sqrt(128)
    float p0 = __expf(d0 * S - 8.0f);
    float p1 = __expf(d1 * S - 8.0f);
    float p2 = __expf(d2 * S - 8.0f);
    float p3 = __expf(d3 * S - 8.0f);
    if (count < 2) p1 = 0.0f;
    if (count < 3) p2 = 0.0f;
    if (count < 4) p3 = 0.0f;
    s += (p0 + p1) + (p2 + p3);
    uint2 va = ((const uint2*)(Vb + (size_t)j0 * E_))[lane];
    uint2 vb = ((const uint2*)(Vb + (size_t)j1 * E_))[lane];
    uint2 vc = ((const uint2*)(Vb + (size_t)j2 * E_))[lane];
    uint2 vd = ((const uint2*)(Vb + (size_t)j3 * E_))[lane];
    float2 a0, a1;
    a0 = __half22float2(*(__half2*)&va.x); a1 = __half22float2(*(__half2*)&va.y);
    o.x += p0 * a0.x; o.y += p0 * a0.y; o.z += p0 * a1.x; o.w += p0 * a1.y;
    a0 = __half22float2(*(__half2*)&vb.x); a1 = __half22float2(*(__half2*)&vb.y);
    o.x += p1 * a0.x; o.y += p1 * a0.y; o.z += p1 * a1.x; o.w += p1 * a1.y;
    a0 = __half22float2(*(__half2*)&vc.x); a1 = __half22float2(*(__half2*)&vc.y);
    o.x += p2 * a0.x; o.y += p2 * a0.y; o.z += p2 * a1.x; o.w += p2 * a1.y;
    a0 = __half22float2(*(__half2*)&vd.x); a1 = __half22float2(*(__half2*)&vd.y);
    o.x += p3 * a0.x; o.y += p3 * a0.y; o.z += p3 * a1.x; o.w += p3 * a1.y;
}

__device__ __forceinline__ void visit_range(
    const __half* __restrict__ Kb, const __half* __restrict__ Vb,
    int lo, int hi, int st,
    float4 q, int lane, float& s, float4& o)
{
    for (int j = lo; j <= hi; j += 4 * st) {
        int rem = (hi - j) / st + 1;
        int cnt = rem < 4 ? rem : 4;
        int jb = (cnt > 1) ? j + st     : j;
        int jc = (cnt > 2) ? j + 2 * st : j;
        int jd = (cnt > 3) ? j + 3 * st : j;
        visit4(Kb, Vb, j, jb, jc, jd, cnt, q, lane, s, o);
    }
}

__global__ __launch_bounds__(256)
void sparse_attn_kernel() {
    int gw   = (blockIdx.x * blockDim.x + threadIdx.x) >> 5;
    int lane = threadIdx.x & 31;
    int i  = gw & (L_ - 1);
    int bh = gw >> 11;
    int h  = bh & (H_ - 1);
    int b  = bh >> 3;

    const float* Qp = g_Q + ((size_t)(b * L_ + i)) * E_ + h * D_;
    float4 q = ((const float4*)Qp)[lane];
    const __half* Kb = g_Kh + (size_t)b * L_ * E_ + h * D_;
    const __half* Vb = g_Vh + (size_t)b * L_ * E_ + h * D_;

    float s = 0.0f;
    float4 o = make_float4(0.0f, 0.0f, 0.0f, 0.0f);

    int cl = (h == 0) ? 0 : (h <= 2) ? 3 : (h <= 5) ? 1 : 2;

    if (cl == 0) {
        int lo = i - 8; if (lo < 0) lo = 0;
        visit_range(Kb, Vb, lo, i, 1, q, lane, s, o);
    } else if (cl == 3) {
        int lo = i - 16; if (lo < 0) lo = 0;
        visit_range(Kb, Vb, lo, i, 1, q, lane, s, o);
    } else if (cl == 1) {
        int lo = i - 32; if (lo < 0) lo = 0;
        if (lo > 0)
            visit_range(Kb, Vb, 0, lo - 1 - ((lo - 1) & 7), 8, q, lane, s, o);
        visit_range(Kb, Vb, lo, i, 1, q, lane, s, o);
    } else {
        visit_range(Kb, Vb, 0, i - (i & 15), 16, q, lane, s, o);
        int cnt = 0;
#pragma unroll
        for (int t = 0; t < 10; ++t)
            if (c_anchors[t] <= i) ++cnt;
        for (int base = 0; base < cnt; base += 4) {
            int c = cnt - base; if (c > 4) c = 4;
            int a0 = c_anchors[base];
            int a1 = c_anchors[(c > 1) ? base + 1 : base];
            int a2 = c_anchors[(c > 2) ? base + 2 : base];
            int a3 = c_anchors[(c > 3) ? base + 3 : base];
            visit4(Kb, Vb, a0, a1, a2, a3, c, q, lane, s, o);
        }
    }

    float inv = 1.0f / s;
    float* op = g_ctx + ((size_t)(b * L_ + i)) * E_ + h * D_;
    float4 r = make_float4(o.x * inv, o.y * inv, o.z * inv, o.w * inv);
    ((float4*)op)[lane] = r;
}

// ---------------------------------------------------------------------------
extern "C" void kernel_launch(void* const* d_in, const int* in_sizes, int n_in,
                              void* d_out, int out_size) {
    const float* query = (const float*)d_in[0];
    const float* key_  = (const float*)d_in[1];
    const float* value = (const float*)d_in[2];
    const float* Wq = (const float*)d_in[3];
    const float* bq = (const float*)d_in[4];
    const float* Wk = (const float*)d_in[5];
    const float* bk = (const float*)d_in[6];
    const float* Wv = (const float*)d_in[7];
    const float* bv = (const float*)d_in[8];
    const float* Wo = (const float*)d_in[9];
    const float* bo = (const float*)d_in[10];
    float* out = (float*)d_out;

    float *Qd, *Cd;
    __half *Khd, *Vhd;
    cudaGetSymbolAddress((void**)&Qd, g_Q);
    cudaGetSymbolAddress((void**)&Khd, g_Kh);
    cudaGetSymbolAddress((void**)&Vhd, g_Vh);
    cudaGetSymbolAddress((void**)&Cd, g_ctx);

    dim3 ggrid(E_ / 128, (B_ * L_) / 128);   // 8 x 32 = 256 CTAs

    gemm_tc_kernel<false><<<ggrid, 256>>>(query, Wq, bq, Qd);
    gemm_tc_kernel<true ><<<ggrid, 256>>>(key_,  Wk, bk, Khd);
    gemm_tc_kernel<true ><<<ggrid, 256>>>(value, Wv, bv, Vhd);

    int total_warps = B_ * H_ * L_;                 // 32768
    sparse_attn_kernel<<<total_warps * 32 / 256, 256>>>();

    gemm_tc_kernel<false><<<ggrid, 256>>>(Cd, Wo, bo, out);
}

// round 9
// speedup vs baseline: 1.3492x; 1.2655x over previous
#include <cuda_runtime.h>
#include <cuda_fp16.h>
#include <cstdint>
#include <math.h>

#define B_ 2
#define L_ 2048
#define E_ 1024
#define H_ 8
#define D_ 128

// Scratch (allocation-free rule: __device__ globals)
__device__ __half g_Qh[B_ * L_ * E_];
__device__ __half g_Kh[B_ * L_ * E_];
__device__ __half g_Vh[B_ * L_ * E_];
__device__ float  g_ctx[B_ * L_ * E_];

__constant__ int c_anchors[10] = {204, 409, 614, 781, 1023, 1265, 1432, 1637, 1842, 2047};

// ===========================================================================
// helpers
// ===========================================================================
__device__ __forceinline__ uint32_t smem_u32(const void* p) {
    uint32_t a;
    asm("{ .reg .u64 t; cvta.to.shared.u64 t, %1; cvt.u32.u64 %0, t; }" : "=r"(a) : "l"(p));
    return a;
}

__device__ __forceinline__ uint32_t pack_bf16x2(float x0, float x1) {
    uint32_t r;
    asm("cvt.rn.bf16x2.f32 %0, %2, %1;" : "=r"(r) : "f"(x0), "f"(x1));
    return r;
}

// pack two f32 -> f16x2 (x0 -> low half, x1 -> high half)
__device__ __forceinline__ uint32_t pack_f16x2(float x0, float x1) {
    uint32_t r;
    asm("cvt.rn.f16x2.f32 %0, %2, %1;" : "=r"(r) : "f"(x0), "f"(x1));
    return r;
}

__device__ __forceinline__ void ldsm4(uint32_t* r, uint32_t addr) {
    asm volatile("ldmatrix.sync.aligned.m8n8.x4.shared.b16 {%0,%1,%2,%3}, [%4];"
                 : "=r"(r[0]), "=r"(r[1]), "=r"(r[2]), "=r"(r[3]) : "r"(addr));
}

__device__ __forceinline__ void ldsm4t(uint32_t* r, uint32_t addr) {
    asm volatile("ldmatrix.sync.aligned.m8n8.x4.trans.shared.b16 {%0,%1,%2,%3}, [%4];"
                 : "=r"(r[0]), "=r"(r[1]), "=r"(r[2]), "=r"(r[3]) : "r"(addr));
}

__device__ __forceinline__ void mma_bf16(float* d, const uint32_t* a, const uint32_t* b) {
    asm volatile(
        "mma.sync.aligned.m16n8k16.row.col.f32.bf16.bf16.f32 "
        "{%0,%1,%2,%3}, {%4,%5,%6,%7}, {%8,%9}, {%0,%1,%2,%3};"
        : "+f"(d[0]), "+f"(d[1]), "+f"(d[2]), "+f"(d[3])
        : "r"(a[0]), "r"(a[1]), "r"(a[2]), "r"(a[3]), "r"(b[0]), "r"(b[1]));
}

__device__ __forceinline__ void mma_f16(float* d, const uint32_t* a, const uint32_t* b) {
    asm volatile(
        "mma.sync.aligned.m16n8k16.row.col.f32.f16.f16.f32 "
        "{%0,%1,%2,%3}, {%4,%5,%6,%7}, {%8,%9}, {%0,%1,%2,%3};"
        : "+f"(d[0]), "+f"(d[1]), "+f"(d[2]), "+f"(d[3])
        : "r"(a[0]), "r"(a[1]), "r"(a[2]), "r"(a[3]), "r"(b[0]), "r"(b[1]));
}

#define CP16(dst, src) \
    asm volatile("cp.async.cg.shared.global [%0], [%1], 16;" :: "r"(dst), "l"(src) : "memory")

// ===========================================================================
// Tensor-core GEMM (mma.sync, split-bf16 hi/lo inline, fp32 accum):
//   C[4096,1024] = A[4096,1024] @ W[1024,1024]^T + bias
// CTA 128x128, 8 warps (2m x 4n), warp tile 64x32, BK=32. (validated R5/R7)
// ===========================================================================
#define LDA 80
#define T_BYTES (128 * LDA)
#define AH_OFF 0
#define AL_OFF (T_BYTES)
#define WH_OFF (2 * T_BYTES)
#define WL_OFF (3 * T_BYTES)

template <bool HALF_OUT>
__global__ __launch_bounds__(256, 1)
void gemm_tc_kernel(const float* __restrict__ A, const float* __restrict__ W,
                    const float* __restrict__ bias, void* __restrict__ Cout) {
    __shared__ __align__(16) uint8_t sm[4 * T_BYTES];
    uint32_t sb = smem_u32(sm);

    int tid = threadIdx.x;
    int lane = tid & 31;
    int wid = tid >> 5;
    int warpM = wid >> 2;
    int warpN = wid & 3;

    const float* Ag = A + (size_t)blockIdx.y * 128 * 1024;
    const float* Wg = W + (size_t)blockIdx.x * 128 * 1024;

    int r0 = tid >> 3;
    int c4 = tid & 7;

    float4 pa[4], pw[4];
#pragma unroll
    for (int i = 0; i < 4; ++i) {
        pa[i] = *(const float4*)(Ag + (size_t)(r0 + i * 32) * 1024 + c4 * 4);
        pw[i] = *(const float4*)(Wg + (size_t)(r0 + i * 32) * 1024 + c4 * 4);
    }

    float acc[4][4][4];
#pragma unroll
    for (int f = 0; f < 4; ++f)
#pragma unroll
        for (int g = 0; g < 4; ++g)
#pragma unroll
            for (int r = 0; r < 4; ++r) acc[f][g][r] = 0.0f;

    uint32_t aRow = (uint32_t)(warpM * 64) + (lane & 15);
    uint32_t aAddrBase = aRow * LDA + ((lane >> 4) << 4);
    uint32_t bRow = (uint32_t)(warpN * 32) + (lane & 7) + ((lane >> 4) << 3);
    uint32_t bAddrBase = bRow * LDA + (((lane >> 3) & 1) << 4);

    for (int kt = 0; kt < 32; ++kt) {
#pragma unroll
        for (int i = 0; i < 4; ++i) {
            uint32_t so = (uint32_t)(r0 + i * 32) * LDA + c4 * 8;
            float4 v = pa[i];
            uint32_t h0 = pack_bf16x2(v.x, v.y);
            uint32_t h1 = pack_bf16x2(v.z, v.w);
            float l0 = v.x - __uint_as_float(h0 << 16);
            float l1 = v.y - __uint_as_float(h0 & 0xFFFF0000u);
            float l2 = v.z - __uint_as_float(h1 << 16);
            float l3 = v.w - __uint_as_float(h1 & 0xFFFF0000u);
            *(uint2*)(sm + AH_OFF + so) = make_uint2(h0, h1);
            *(uint2*)(sm + AL_OFF + so) = make_uint2(pack_bf16x2(l0, l1), pack_bf16x2(l2, l3));
            v = pw[i];
            h0 = pack_bf16x2(v.x, v.y);
            h1 = pack_bf16x2(v.z, v.w);
            l0 = v.x - __uint_as_float(h0 << 16);
            l1 = v.y - __uint_as_float(h0 & 0xFFFF0000u);
            l2 = v.z - __uint_as_float(h1 << 16);
            l3 = v.w - __uint_as_float(h1 & 0xFFFF0000u);
            *(uint2*)(sm + WH_OFF + so) = make_uint2(h0, h1);
            *(uint2*)(sm + WL_OFF + so) = make_uint2(pack_bf16x2(l0, l1), pack_bf16x2(l2, l3));
        }
        __syncthreads();

        if (kt < 31) {
            int k0 = (kt + 1) * 32;
#pragma unroll
            for (int i = 0; i < 4; ++i) {
                pa[i] = *(const float4*)(Ag + (size_t)(r0 + i * 32) * 1024 + k0 + c4 * 4);
                pw[i] = *(const float4*)(Wg + (size_t)(r0 + i * 32) * 1024 + k0 + c4 * 4);
            }
        }

#pragma unroll
        for (int ks = 0; ks < 2; ++ks) {
            uint32_t koff = ks * 32;
            uint32_t bH[2][4], bL[2][4];
            ldsm4(bH[0], sb + WH_OFF + bAddrBase + koff);
            ldsm4(bH[1], sb + WH_OFF + bAddrBase + 16 * LDA + koff);
            ldsm4(bL[0], sb + WL_OFF + bAddrBase + koff);
            ldsm4(bL[1], sb + WL_OFF + bAddrBase + 16 * LDA + koff);
#pragma unroll
            for (int f = 0; f < 4; ++f) {
                uint32_t aH[4], aL[4];
                ldsm4(aH, sb + AH_OFF + aAddrBase + (uint32_t)(f * 16) * LDA + koff);
                ldsm4(aL, sb + AL_OFF + aAddrBase + (uint32_t)(f * 16) * LDA + koff);
#pragma unroll
                for (int g = 0; g < 4; ++g) {
                    const uint32_t* bh = &bH[g >> 1][(g & 1) * 2];
                    const uint32_t* bl = &bL[g >> 1][(g & 1) * 2];
                    mma_bf16(acc[f][g], aH, bh);
                    mma_bf16(acc[f][g], aL, bh);
                    mma_bf16(acc[f][g], aH, bl);
                }
            }
        }
        __syncthreads();
    }

    int crow = blockIdx.y * 128 + warpM * 64 + (lane >> 2);
    int ccol0 = blockIdx.x * 128 + warpN * 32 + (lane & 3) * 2;
#pragma unroll
    for (int g = 0; g < 4; ++g) {
        int c = ccol0 + g * 8;
        float2 bv = *(const float2*)(bias + c);
#pragma unroll
        for (int f = 0; f < 4; ++f) {
            int r = crow + f * 16;
            float2 o0 = make_float2(acc[f][g][0] + bv.x, acc[f][g][1] + bv.y);
            float2 o1 = make_float2(acc[f][g][2] + bv.x, acc[f][g][3] + bv.y);
            if (HALF_OUT) {
                __half* Ch = (__half*)Cout;
                *(__half2*)(Ch + (size_t)r * 1024 + c) = __floats2half2_rn(o0.x, o0.y);
                *(__half2*)(Ch + (size_t)(r + 8) * 1024 + c) = __floats2half2_rn(o1.x, o1.y);
            } else {
                float* Cf = (float*)Cout;
                *(float2*)(Cf + (size_t)r * 1024 + c) = o0;
                *(float2*)(Cf + (size_t)(r + 8) * 1024 + c) = o1;
            }
        }
    }
}

// ===========================================================================
// MMA sparse attention: CTA = (b, h, 64-row tile). 4 warps x 16 rows.
// Column list (cluster superset) in smem; gather K/V cols; S = Q K^T (f16 mma);
// mask per element; p = exp(s*scale - 2); O += P V (f16 mma, FA2 frag reuse).
// sAcc accumulates the fp16-ROUNDED p values -> normalization consistent
// with the P.V numerator.
// ===========================================================================
#define LDKV 136                 // halves per smem row (272 B, 16B-pad)
#define MAXCOLS 384
#define ATTN_SCALE 0.08838834764831845f

__global__ __launch_bounds__(128, 1)
void attn_mma_kernel() {
    __shared__ int colsSm[MAXCOLS];
    __shared__ __align__(16) __half Ksm[64 * LDKV];
    __shared__ __align__(16) __half Vsm[64 * LDKV];

    int tid = threadIdx.x;
    int lane = tid & 31;
    int w = tid >> 5;

    int bid = blockIdx.x;
    int tile = 31 - (bid >> 4);          // big-i tiles first
    int h = bid & 7;
    int b = (bid >> 3) & 1;
    int i0 = tile * 64;
    int cl = (h == 0) ? 0 : (h <= 2) ? 3 : (h <= 5) ? 1 : 2;

    // ---- build column list (all threads compute identical scalars) ----
    int ncol;
    if (cl == 2) {
        int n16 = ((i0 + 63) >> 4) + 1;
        for (int t = tid; t < n16; t += 128) colsSm[t] = t << 4;
        if (tid < 10) colsSm[n16 + tid] = c_anchors[tid];
        ncol = n16 + 10;
    } else {
        int wr = (cl == 0) ? 8 : (cl == 3) ? 16 : 32;
        int wstart = i0 - wr; if (wstart < 0) wstart = 0;
        int ns = (cl == 1) ? ((wstart + 7) >> 3) : 0;
        int nw = i0 + 63 - wstart + 1;
        if (cl == 1)
            for (int t = tid; t < ns; t += 128) colsSm[t] = t << 3;
        for (int t = tid; t < nw; t += 128) colsSm[ns + t] = wstart + t;
        ncol = ns + nw;
    }
    int npad = (ncol + 63) & ~63;
    for (int t = ncol + tid; t < npad; t += 128) colsSm[t] = 1 << 28;  // sentinel

    // ---- stage Q tile (64x128 f16) into Ksm, extract A-frags ----
    {
        int m = tid >> 1;
        int hf = tid & 1;
        const uint4* src = (const uint4*)(g_Qh + ((size_t)(b * L_ + i0 + m)) * E_ + h * D_ + hf * 64);
        uint4* dst = (uint4*)(Ksm + m * LDKV + hf * 64);
#pragma unroll
        for (int t = 0; t < 8; ++t) dst[t] = src[t];
    }
    __syncthreads();

    uint32_t kb = smem_u32(Ksm);
    uint32_t vb = smem_u32(Vsm);

    uint32_t qf[8][4];
    {
        uint32_t aAddr = kb + (uint32_t)(w * 16 + (lane & 15)) * 272 + ((lane >> 4) << 4);
#pragma unroll
        for (int ks = 0; ks < 8; ++ks)
            ldsm4(qf[ks], aAddr + ks * 32);
    }
    __syncthreads();

    // ---- main loop over 64-column chunks ----
    float O[16][4];
#pragma unroll
    for (int nb = 0; nb < 16; ++nb)
#pragma unroll
        for (int r = 0; r < 4; ++r) O[nb][r] = 0.0f;
    float sAcc0 = 0.0f, sAcc1 = 0.0f;

    int r_lo = i0 + w * 16 + (lane >> 2);
    int r_hi = r_lo + 8;

    int nchunks = npad >> 6;
    for (int ci = 0; ci < nchunks; ++ci) {
        // gather K/V columns (cp.async, 128B per thread per operand)
        {
            int slot = tid >> 1;
            int hf = tid & 1;
            int j = colsSm[ci * 64 + slot];
            int jg = (j < L_) ? j : 0;
            size_t go = ((size_t)(b * L_ + jg)) * E_ + h * D_ + hf * 64;
            uint32_t dK = kb + (uint32_t)slot * 272 + hf * 128;
            uint32_t dV = vb + (uint32_t)slot * 272 + hf * 128;
            const __half* sK = g_Kh + go;
            const __half* sV = g_Vh + go;
#pragma unroll
            for (int t = 0; t < 8; ++t) {
                CP16(dK + t * 16, sK + t * 8);
                CP16(dV + t * 16, sV + t * 8);
            }
            asm volatile("cp.async.commit_group;" ::: "memory");
            asm volatile("cp.async.wait_group 0;" ::: "memory");
        }
        __syncthreads();

        // S = Q K^T  (16 rows x 64 cols per warp)
        float S[8][4];
#pragma unroll
        for (int nb = 0; nb < 8; ++nb)
#pragma unroll
            for (int r = 0; r < 4; ++r) S[nb][r] = 0.0f;

        uint32_t bBase = kb + (uint32_t)((lane & 7) + ((lane >> 4) << 3)) * 272 + (((lane >> 3) & 1) << 4);
#pragma unroll
        for (int g2 = 0; g2 < 4; ++g2) {
#pragma unroll
            for (int ks = 0; ks < 8; ++ks) {
                uint32_t bf[4];
                ldsm4(bf, bBase + (uint32_t)(g2 * 16) * 272 + ks * 32);
                mma_f16(S[g2 * 2 + 0], qf[ks], bf + 0);
                mma_f16(S[g2 * 2 + 1], qf[ks], bf + 2);
            }
        }

        // mask + exp + pack P (accumulate the fp16-rounded p values)
        uint32_t aPlo[8], aPhi[8];
#pragma unroll
        for (int nb = 0; nb < 8; ++nb) {
            int cidx = ci * 64 + nb * 8 + ((lane & 3) << 1);
            int j0 = colsSm[cidx];
            int j1 = colsSm[cidx + 1];
            bool ok00, ok01, ok10, ok11;
            if (cl == 0) {
                ok00 = (j0 <= r_lo) && (r_lo - j0 <= 8);
                ok01 = (j1 <= r_lo) && (r_lo - j1 <= 8);
                ok10 = (j0 <= r_hi) && (r_hi - j0 <= 8);
                ok11 = (j1 <= r_hi) && (r_hi - j1 <= 8);
            } else if (cl == 3) {
                ok00 = (j0 <= r_lo) && (r_lo - j0 <= 16);
                ok01 = (j1 <= r_lo) && (r_lo - j1 <= 16);
                ok10 = (j0 <= r_hi) && (r_hi - j0 <= 16);
                ok11 = (j1 <= r_hi) && (r_hi - j1 <= 16);
            } else if (cl == 1) {
                ok00 = (j0 <= r_lo) && ((r_lo - j0 <= 32) || ((j0 & 7) == 0));
                ok01 = (j1 <= r_lo) && ((r_lo - j1 <= 32) || ((j1 & 7) == 0));
                ok10 = (j0 <= r_hi) && ((r_hi - j0 <= 32) || ((j0 & 7) == 0));
                ok11 = (j1 <= r_hi) && ((r_hi - j1 <= 32) || ((j1 & 7) == 0));
            } else {
                ok00 = (j0 <= r_lo);
                ok01 = (j1 <= r_lo);
                ok10 = (j0 <= r_hi);
                ok11 = (j1 <= r_hi);
            }
            float p00 = ok00 ? __expf(fmaf(S[nb][0], ATTN_SCALE, -2.0f)) : 0.0f;
            float p01 = ok01 ? __expf(fmaf(S[nb][1], ATTN_SCALE, -2.0f)) : 0.0f;
            float p10 = ok10 ? __expf(fmaf(S[nb][2], ATTN_SCALE, -2.0f)) : 0.0f;
            float p11 = ok11 ? __expf(fmaf(S[nb][3], ATTN_SCALE, -2.0f)) : 0.0f;
            uint32_t plo = pack_f16x2(p00, p01);
            uint32_t phi = pack_f16x2(p10, p11);
            aPlo[nb] = plo;
            aPhi[nb] = phi;
            // accumulate the ROUNDED values (consistent with P.V numerator)
            float2 rlo = __half22float2(*(__half2*)&plo);
            float2 rhi = __half22float2(*(__half2*)&phi);
            sAcc0 += rlo.x + rlo.y;
            sAcc1 += rhi.x + rhi.y;
        }

        // O += P V
#pragma unroll
        for (int ks = 0; ks < 4; ++ks) {
            uint32_t aP[4] = {aPlo[2 * ks], aPhi[2 * ks], aPlo[2 * ks + 1], aPhi[2 * ks + 1]};
            uint32_t vAddr = vb + (uint32_t)(ks * 16 + (lane & 7) + (((lane >> 3) & 1) << 3)) * 272
                           + ((lane >> 4) << 4);
#pragma unroll
            for (int gv = 0; gv < 8; ++gv) {
                uint32_t vf[4];
                ldsm4t(vf, vAddr + gv * 32);
                mma_f16(O[gv * 2 + 0], aP, vf + 0);
                mma_f16(O[gv * 2 + 1], aP, vf + 2);
            }
        }
        __syncthreads();
    }

    // ---- epilogue: normalize + store fp32 ctx ----
    sAcc0 += __shfl_xor_sync(0xffffffffu, sAcc0, 1);
    sAcc0 += __shfl_xor_sync(0xffffffffu, sAcc0, 2);
    sAcc1 += __shfl_xor_sync(0xffffffffu, sAcc1, 1);
    sAcc1 += __shfl_xor_sync(0xffffffffu, sAcc1, 2);
    float inv0 = 1.0f / sAcc0;
    float inv1 = 1.0f / sAcc1;

    float* out0 = g_ctx + ((size_t)(b * L_ + r_lo)) * E_ + h * D_;
    float* out1 = g_ctx + ((size_t)(b * L_ + r_hi)) * E_ + h * D_;
#pragma unroll
    for (int nb = 0; nb < 16; ++nb) {
        int col = nb * 8 + ((lane & 3) << 1);
        *(float2*)(out0 + col) = make_float2(O[nb][0] * inv0, O[nb][1] * inv0);
        *(float2*)(out1 + col) = make_float2(O[nb][2] * inv1, O[nb][3] * inv1);
    }
}

// ---------------------------------------------------------------------------
extern "C" void kernel_launch(void* const* d_in, const int* in_sizes, int n_in,
                              void* d_out, int out_size) {
    const float* query = (const float*)d_in[0];
    const float* key_  = (const float*)d_in[1];
    const float* value = (const float*)d_in[2];
    const float* Wq = (const float*)d_in[3];
    const float* bq = (const float*)d_in[4];
    const float* Wk = (const float*)d_in[5];
    const float* bk = (const float*)d_in[6];
    const float* Wv = (const float*)d_in[7];
    const float* bv = (const float*)d_in[8];
    const float* Wo = (const float*)d_in[9];
    const float* bo = (const float*)d_in[10];
    float* out = (float*)d_out;

    float* Cd;
    __half *Qhd, *Khd, *Vhd;
    cudaGetSymbolAddress((void**)&Qhd, g_Qh);
    cudaGetSymbolAddress((void**)&Khd, g_Kh);
    cudaGetSymbolAddress((void**)&Vhd, g_Vh);
    cudaGetSymbolAddress((void**)&Cd, g_ctx);

    dim3 ggrid(E_ / 128, (B_ * L_) / 128);   // 8 x 32 = 256 CTAs

    gemm_tc_kernel<true ><<<ggrid, 256>>>(query, Wq, bq, Qhd);
    gemm_tc_kernel<true ><<<ggrid, 256>>>(key_,  Wk, bk, Khd);
    gemm_tc_kernel<true ><<<ggrid, 256>>>(value, Wv, bv, Vhd);

    attn_mma_kernel<<<B_ * H_ * (L_ / 64), 128>>>();   // 512 CTAs

    gemm_tc_kernel<false><<<ggrid, 256>>>(Cd, Wo, bo, out);
}

// round 11
// speedup vs baseline: 1.5269x; 1.1317x over previous
#include <cuda_runtime.h>
#include <cuda_fp16.h>
#include <cstdint>
#include <math.h>

#define B_ 2
#define L_ 2048
#define E_ 1024
#define H_ 8
#define D_ 128

// Scratch (allocation-free rule: __device__ globals)
__device__ __half g_Qh[B_ * L_ * E_];
__device__ __half g_Kh[B_ * L_ * E_];
__device__ __half g_Vh[B_ * L_ * E_];
__device__ float  g_ctx[B_ * L_ * E_];

__constant__ int c_anchors[10] = {204, 409, 614, 781, 1023, 1265, 1432, 1637, 1842, 2047};

// ===========================================================================
// helpers
// ===========================================================================
__device__ __forceinline__ uint32_t smem_u32(const void* p) {
    uint32_t a;
    asm("{ .reg .u64 t; cvta.to.shared.u64 t, %1; cvt.u32.u64 %0, t; }" : "=r"(a) : "l"(p));
    return a;
}

__device__ __forceinline__ uint32_t pack_bf16x2(float x0, float x1) {
    uint32_t r;
    asm("cvt.rn.bf16x2.f32 %0, %2, %1;" : "=r"(r) : "f"(x0), "f"(x1));
    return r;
}

__device__ __forceinline__ uint32_t pack_f16x2(float x0, float x1) {
    uint32_t r;
    asm("cvt.rn.f16x2.f32 %0, %2, %1;" : "=r"(r) : "f"(x0), "f"(x1));
    return r;
}

__device__ __forceinline__ uint32_t to_tf32(float x) {
    uint32_t r;
    asm("cvt.rna.tf32.f32 %0, %1;" : "=r"(r) : "f"(x));
    return r;
}

__device__ __forceinline__ void ldsm4(uint32_t* r, uint32_t addr) {
    asm volatile("ldmatrix.sync.aligned.m8n8.x4.shared.b16 {%0,%1,%2,%3}, [%4];"
                 : "=r"(r[0]), "=r"(r[1]), "=r"(r[2]), "=r"(r[3]) : "r"(addr));
}

__device__ __forceinline__ void ldsm4t(uint32_t* r, uint32_t addr) {
    asm volatile("ldmatrix.sync.aligned.m8n8.x4.trans.shared.b16 {%0,%1,%2,%3}, [%4];"
                 : "=r"(r[0]), "=r"(r[1]), "=r"(r[2]), "=r"(r[3]) : "r"(addr));
}

__device__ __forceinline__ void mma_bf16(float* d, const uint32_t* a, const uint32_t* b) {
    asm volatile(
        "mma.sync.aligned.m16n8k16.row.col.f32.bf16.bf16.f32 "
        "{%0,%1,%2,%3}, {%4,%5,%6,%7}, {%8,%9}, {%0,%1,%2,%3};"
        : "+f"(d[0]), "+f"(d[1]), "+f"(d[2]), "+f"(d[3])
        : "r"(a[0]), "r"(a[1]), "r"(a[2]), "r"(a[3]), "r"(b[0]), "r"(b[1]));
}

__device__ __forceinline__ void mma_f16(float* d, const uint32_t* a, const uint32_t* b) {
    asm volatile(
        "mma.sync.aligned.m16n8k16.row.col.f32.f16.f16.f32 "
        "{%0,%1,%2,%3}, {%4,%5,%6,%7}, {%8,%9}, {%0,%1,%2,%3};"
        : "+f"(d[0]), "+f"(d[1]), "+f"(d[2]), "+f"(d[3])
        : "r"(a[0]), "r"(a[1]), "r"(a[2]), "r"(a[3]), "r"(b[0]), "r"(b[1]));
}

__device__ __forceinline__ void mma_tf32(float* d, const uint32_t* a, const uint32_t* b) {
    asm volatile(
        "mma.sync.aligned.m16n8k8.row.col.f32.tf32.tf32.f32 "
        "{%0,%1,%2,%3}, {%4,%5,%6,%7}, {%8,%9}, {%0,%1,%2,%3};"
        : "+f"(d[0]), "+f"(d[1]), "+f"(d[2]), "+f"(d[3])
        : "r"(a[0]), "r"(a[1]), "r"(a[2]), "r"(a[3]), "r"(b[0]), "r"(b[1]));
}

#define CP16(dst, src) \
    asm volatile("cp.async.cg.shared.global [%0], [%1], 16;" :: "r"(dst), "l"(src) : "memory")

// ===========================================================================
// TF32 single-pass GEMM: C = A @ W^T + bias  (for Q/K/V projections)
// CTA 128x128, 8 warps (2m x 4n), warp tile 64x32, BK=32, m16n8k8 tf32.
// smem stride 36 words -> all frag lds.32 conflict-free (bank = 4*gid+tq).
// ===========================================================================
#define TLDW 36

__global__ __launch_bounds__(256, 1)
void gemm_tf32_kernel(const float* __restrict__ A, const float* __restrict__ W,
                      const float* __restrict__ bias, __half* __restrict__ Cout) {
    __shared__ __align__(16) float Asm[128 * TLDW];
    __shared__ __align__(16) float Wsm[128 * TLDW];

    int tid = threadIdx.x;
    int lane = tid & 31;
    int wid = tid >> 5;
    int warpM = wid >> 2;
    int warpN = wid & 3;
    int gid = lane >> 2;      // 0..7
    int tq  = lane & 3;       // 0..3

    const float* Ag = A + (size_t)blockIdx.y * 128 * 1024;
    const float* Wg = W + (size_t)blockIdx.x * 128 * 1024;

    int r0 = tid >> 3;        // 0..31
    int c4 = tid & 7;         // float4 col

    float4 pa[4], pw[4];
#pragma unroll
    for (int i = 0; i < 4; ++i) {
        pa[i] = *(const float4*)(Ag + (size_t)(r0 + i * 32) * 1024 + c4 * 4);
        pw[i] = *(const float4*)(Wg + (size_t)(r0 + i * 32) * 1024 + c4 * 4);
    }

    float acc[4][4][4];
#pragma unroll
    for (int f = 0; f < 4; ++f)
#pragma unroll
        for (int g = 0; g < 4; ++g)
#pragma unroll
            for (int r = 0; r < 4; ++r) acc[f][g][r] = 0.0f;

    for (int kt = 0; kt < 32; ++kt) {
        // stage + convert to tf32 (rna)
#pragma unroll
        for (int i = 0; i < 4; ++i) {
            int so = (r0 + i * 32) * TLDW + c4 * 4;
            float4 v = pa[i];
            uint4 t;
            t.x = to_tf32(v.x); t.y = to_tf32(v.y); t.z = to_tf32(v.z); t.w = to_tf32(v.w);
            *(uint4*)(Asm + so) = t;
            v = pw[i];
            t.x = to_tf32(v.x); t.y = to_tf32(v.y); t.z = to_tf32(v.z); t.w = to_tf32(v.w);
            *(uint4*)(Wsm + so) = t;
        }
        __syncthreads();

        if (kt < 31) {
            int k0 = (kt + 1) * 32;
#pragma unroll
            for (int i = 0; i < 4; ++i) {
                pa[i] = *(const float4*)(Ag + (size_t)(r0 + i * 32) * 1024 + k0 + c4 * 4);
                pw[i] = *(const float4*)(Wg + (size_t)(r0 + i * 32) * 1024 + k0 + c4 * 4);
            }
        }

#pragma unroll
        for (int ks = 0; ks < 4; ++ks) {
            int kc = ks * 8 + tq;
            uint32_t bfr[4][2];
#pragma unroll
            for (int g = 0; g < 4; ++g) {
                int bn = (warpN * 32 + g * 8 + gid) * TLDW + kc;
                bfr[g][0] = __float_as_uint(Wsm[bn]);
                bfr[g][1] = __float_as_uint(Wsm[bn + 4]);
            }
#pragma unroll
            for (int f = 0; f < 4; ++f) {
                int ar = (warpM * 64 + f * 16 + gid) * TLDW + kc;
                uint32_t a[4];
                a[0] = __float_as_uint(Asm[ar]);
                a[1] = __float_as_uint(Asm[ar + 8 * TLDW]);
                a[2] = __float_as_uint(Asm[ar + 4]);
                a[3] = __float_as_uint(Asm[ar + 8 * TLDW + 4]);
#pragma unroll
                for (int g = 0; g < 4; ++g)
                    mma_tf32(acc[f][g], a, bfr[g]);
            }
        }
        __syncthreads();
    }

    int crow = blockIdx.y * 128 + warpM * 64 + (lane >> 2);
    int ccol0 = blockIdx.x * 128 + warpN * 32 + (lane & 3) * 2;
#pragma unroll
    for (int g = 0; g < 4; ++g) {
        int c = ccol0 + g * 8;
        float2 bv = *(const float2*)(bias + c);
#pragma unroll
        for (int f = 0; f < 4; ++f) {
            int r = crow + f * 16;
            *(__half2*)(Cout + (size_t)r * 1024 + c) =
                __floats2half2_rn(acc[f][g][0] + bv.x, acc[f][g][1] + bv.y);
            *(__half2*)(Cout + (size_t)(r + 8) * 1024 + c) =
                __floats2half2_rn(acc[f][g][2] + bv.x, acc[f][g][3] + bv.y);
        }
    }
}

// ===========================================================================
// Split-bf16 GEMM (hi/lo, 3 mma) — kept for the Wo projection (full precision)
// ===========================================================================
#define LDA 80
#define T_BYTES (128 * LDA)
#define AH_OFF 0
#define AL_OFF (T_BYTES)
#define WH_OFF (2 * T_BYTES)
#define WL_OFF (3 * T_BYTES)

__global__ __launch_bounds__(256, 1)
void gemm_tc_kernel(const float* __restrict__ A, const float* __restrict__ W,
                    const float* __restrict__ bias, float* __restrict__ Cout) {
    __shared__ __align__(16) uint8_t sm[4 * T_BYTES];
    uint32_t sb = smem_u32(sm);

    int tid = threadIdx.x;
    int lane = tid & 31;
    int wid = tid >> 5;
    int warpM = wid >> 2;
    int warpN = wid & 3;

    const float* Ag = A + (size_t)blockIdx.y * 128 * 1024;
    const float* Wg = W + (size_t)blockIdx.x * 128 * 1024;

    int r0 = tid >> 3;
    int c4 = tid & 7;

    float4 pa[4], pw[4];
#pragma unroll
    for (int i = 0; i < 4; ++i) {
        pa[i] = *(const float4*)(Ag + (size_t)(r0 + i * 32) * 1024 + c4 * 4);
        pw[i] = *(const float4*)(Wg + (size_t)(r0 + i * 32) * 1024 + c4 * 4);
    }

    float acc[4][4][4];
#pragma unroll
    for (int f = 0; f < 4; ++f)
#pragma unroll
        for (int g = 0; g < 4; ++g)
#pragma unroll
            for (int r = 0; r < 4; ++r) acc[f][g][r] = 0.0f;

    uint32_t aRow = (uint32_t)(warpM * 64) + (lane & 15);
    uint32_t aAddrBase = aRow * LDA + ((lane >> 4) << 4);
    uint32_t bRow = (uint32_t)(warpN * 32) + (lane & 7) + ((lane >> 4) << 3);
    uint32_t bAddrBase = bRow * LDA + (((lane >> 3) & 1) << 4);

    for (int kt = 0; kt < 32; ++kt) {
#pragma unroll
        for (int i = 0; i < 4; ++i) {
            uint32_t so = (uint32_t)(r0 + i * 32) * LDA + c4 * 8;
            float4 v = pa[i];
            uint32_t h0 = pack_bf16x2(v.x, v.y);
            uint32_t h1 = pack_bf16x2(v.z, v.w);
            float l0 = v.x - __uint_as_float(h0 << 16);
            float l1 = v.y - __uint_as_float(h0 & 0xFFFF0000u);
            float l2 = v.z - __uint_as_float(h1 << 16);
            float l3 = v.w - __uint_as_float(h1 & 0xFFFF0000u);
            *(uint2*)(sm + AH_OFF + so) = make_uint2(h0, h1);
            *(uint2*)(sm + AL_OFF + so) = make_uint2(pack_bf16x2(l0, l1), pack_bf16x2(l2, l3));
            v = pw[i];
            h0 = pack_bf16x2(v.x, v.y);
            h1 = pack_bf16x2(v.z, v.w);
            l0 = v.x - __uint_as_float(h0 << 16);
            l1 = v.y - __uint_as_float(h0 & 0xFFFF0000u);
            l2 = v.z - __uint_as_float(h1 << 16);
            l3 = v.w - __uint_as_float(h1 & 0xFFFF0000u);
            *(uint2*)(sm + WH_OFF + so) = make_uint2(h0, h1);
            *(uint2*)(sm + WL_OFF + so) = make_uint2(pack_bf16x2(l0, l1), pack_bf16x2(l2, l3));
        }
        __syncthreads();

        if (kt < 31) {
            int k0 = (kt + 1) * 32;
#pragma unroll
            for (int i = 0; i < 4; ++i) {
                pa[i] = *(const float4*)(Ag + (size_t)(r0 + i * 32) * 1024 + k0 + c4 * 4);
                pw[i] = *(const float4*)(Wg + (size_t)(r0 + i * 32) * 1024 + k0 + c4 * 4);
            }
        }

#pragma unroll
        for (int ks = 0; ks < 2; ++ks) {
            uint32_t koff = ks * 32;
            uint32_t bH[2][4], bL[2][4];
            ldsm4(bH[0], sb + WH_OFF + bAddrBase + koff);
            ldsm4(bH[1], sb + WH_OFF + bAddrBase + 16 * LDA + koff);
            ldsm4(bL[0], sb + WL_OFF + bAddrBase + koff);
            ldsm4(bL[1], sb + WL_OFF + bAddrBase + 16 * LDA + koff);
#pragma unroll
            for (int f = 0; f < 4; ++f) {
                uint32_t aH[4], aL[4];
                ldsm4(aH, sb + AH_OFF + aAddrBase + (uint32_t)(f * 16) * LDA + koff);
                ldsm4(aL, sb + AL_OFF + aAddrBase + (uint32_t)(f * 16) * LDA + koff);
#pragma unroll
                for (int g = 0; g < 4; ++g) {
                    const uint32_t* bh = &bH[g >> 1][(g & 1) * 2];
                    const uint32_t* bl = &bL[g >> 1][(g & 1) * 2];
                    mma_bf16(acc[f][g], aH, bh);
                    mma_bf16(acc[f][g], aL, bh);
                    mma_bf16(acc[f][g], aH, bl);
                }
            }
        }
        __syncthreads();
    }

    int crow = blockIdx.y * 128 + warpM * 64 + (lane >> 2);
    int ccol0 = blockIdx.x * 128 + warpN * 32 + (lane & 3) * 2;
#pragma unroll
    for (int g = 0; g < 4; ++g) {
        int c = ccol0 + g * 8;
        float2 bv = *(const float2*)(bias + c);
#pragma unroll
        for (int f = 0; f < 4; ++f) {
            int r = crow + f * 16;
            *(float2*)(Cout + (size_t)r * 1024 + c) =
                make_float2(acc[f][g][0] + bv.x, acc[f][g][1] + bv.y);
            *(float2*)(Cout + (size_t)(r + 8) * 1024 + c) =
                make_float2(acc[f][g][2] + bv.x, acc[f][g][3] + bv.y);
        }
    }
}

// ===========================================================================
// MMA sparse attention (R9, passing — unchanged)
// ===========================================================================
#define LDKV 136
#define MAXCOLS 384
#define ATTN_SCALE 0.08838834764831845f

__global__ __launch_bounds__(128, 1)
void attn_mma_kernel() {
    __shared__ int colsSm[MAXCOLS];
    __shared__ __align__(16) __half Ksm[64 * LDKV];
    __shared__ __align__(16) __half Vsm[64 * LDKV];

    int tid = threadIdx.x;
    int lane = tid & 31;
    int w = tid >> 5;

    int bid = blockIdx.x;
    int tile = 31 - (bid >> 4);
    int h = bid & 7;
    int b = (bid >> 3) & 1;
    int i0 = tile * 64;
    int cl = (h == 0) ? 0 : (h <= 2) ? 3 : (h <= 5) ? 1 : 2;

    int ncol;
    if (cl == 2) {
        int n16 = ((i0 + 63) >> 4) + 1;
        for (int t = tid; t < n16; t += 128) colsSm[t] = t << 4;
        if (tid < 10) colsSm[n16 + tid] = c_anchors[tid];
        ncol = n16 + 10;
    } else {
        int wr = (cl == 0) ? 8 : (cl == 3) ? 16 : 32;
        int wstart = i0 - wr; if (wstart < 0) wstart = 0;
        int ns = (cl == 1) ? ((wstart + 7) >> 3) : 0;
        int nw = i0 + 63 - wstart + 1;
        if (cl == 1)
            for (int t = tid; t < ns; t += 128) colsSm[t] = t << 3;
        for (int t = tid; t < nw; t += 128) colsSm[ns + t] = wstart + t;
        ncol = ns + nw;
    }
    int npad = (ncol + 63) & ~63;
    for (int t = ncol + tid; t < npad; t += 128) colsSm[t] = 1 << 28;

    {
        int m = tid >> 1;
        int hf = tid & 1;
        const uint4* src = (const uint4*)(g_Qh + ((size_t)(b * L_ + i0 + m)) * E_ + h * D_ + hf * 64);
        uint4* dst = (uint4*)(Ksm + m * LDKV + hf * 64);
#pragma unroll
        for (int t = 0; t < 8; ++t) dst[t] = src[t];
    }
    __syncthreads();

    uint32_t kb = smem_u32(Ksm);
    uint32_t vb = smem_u32(Vsm);

    uint32_t qf[8][4];
    {
        uint32_t aAddr = kb + (uint32_t)(w * 16 + (lane & 15)) * 272 + ((lane >> 4) << 4);
#pragma unroll
        for (int ks = 0; ks < 8; ++ks)
            ldsm4(qf[ks], aAddr + ks * 32);
    }
    __syncthreads();

    float O[16][4];
#pragma unroll
    for (int nb = 0; nb < 16; ++nb)
#pragma unroll
        for (int r = 0; r < 4; ++r) O[nb][r] = 0.0f;
    float sAcc0 = 0.0f, sAcc1 = 0.0f;

    int r_lo = i0 + w * 16 + (lane >> 2);
    int r_hi = r_lo + 8;

    int nchunks = npad >> 6;
    for (int ci = 0; ci < nchunks; ++ci) {
        {
            int slot = tid >> 1;
            int hf = tid & 1;
            int j = colsSm[ci * 64 + slot];
            int jg = (j < L_) ? j : 0;
            size_t go = ((size_t)(b * L_ + jg)) * E_ + h * D_ + hf * 64;
            uint32_t dK = kb + (uint32_t)slot * 272 + hf * 128;
            uint32_t dV = vb + (uint32_t)slot * 272 + hf * 128;
            const __half* sK = g_Kh + go;
            const __half* sV = g_Vh + go;
#pragma unroll
            for (int t = 0; t < 8; ++t) {
                CP16(dK + t * 16, sK + t * 8);
                CP16(dV + t * 16, sV + t * 8);
            }
            asm volatile("cp.async.commit_group;" ::: "memory");
            asm volatile("cp.async.wait_group 0;" ::: "memory");
        }
        __syncthreads();

        float S[8][4];
#pragma unroll
        for (int nb = 0; nb < 8; ++nb)
#pragma unroll
            for (int r = 0; r < 4; ++r) S[nb][r] = 0.0f;

        uint32_t bBase = kb + (uint32_t)((lane & 7) + ((lane >> 4) << 3)) * 272 + (((lane >> 3) & 1) << 4);
#pragma unroll
        for (int g2 = 0; g2 < 4; ++g2) {
#pragma unroll
            for (int ks = 0; ks < 8; ++ks) {
                uint32_t bf[4];
                ldsm4(bf, bBase + (uint32_t)(g2 * 16) * 272 + ks * 32);
                mma_f16(S[g2 * 2 + 0], qf[ks], bf + 0);
                mma_f16(S[g2 * 2 + 1], qf[ks], bf + 2);
            }
        }

        uint32_t aPlo[8], aPhi[8];
#pragma unroll
        for (int nb = 0; nb < 8; ++nb) {
            int cidx = ci * 64 + nb * 8 + ((lane & 3) << 1);
            int j0 = colsSm[cidx];
            int j1 = colsSm[cidx + 1];
            bool ok00, ok01, ok10, ok11;
            if (cl == 0) {
                ok00 = (j0 <= r_lo) && (r_lo - j0 <= 8);
                ok01 = (j1 <= r_lo) && (r_lo - j1 <= 8);
                ok10 = (j0 <= r_hi) && (r_hi - j0 <= 8);
                ok11 = (j1 <= r_hi) && (r_hi - j1 <= 8);
            } else if (cl == 3) {
                ok00 = (j0 <= r_lo) && (r_lo - j0 <= 16);
                ok01 = (j1 <= r_lo) && (r_lo - j1 <= 16);
                ok10 = (j0 <= r_hi) && (r_hi - j0 <= 16);
                ok11 = (j1 <= r_hi) && (r_hi - j1 <= 16);
            } else if (cl == 1) {
                ok00 = (j0 <= r_lo) && ((r_lo - j0 <= 32) || ((j0 & 7) == 0));
                ok01 = (j1 <= r_lo) && ((r_lo - j1 <= 32) || ((j1 & 7) == 0));
                ok10 = (j0 <= r_hi) && ((r_hi - j0 <= 32) || ((j0 & 7) == 0));
                ok11 = (j1 <= r_hi) && ((r_hi - j1 <= 32) || ((j1 & 7) == 0));
            } else {
                ok00 = (j0 <= r_lo);
                ok01 = (j1 <= r_lo);
                ok10 = (j0 <= r_hi);
                ok11 = (j1 <= r_hi);
            }
            float p00 = ok00 ? __expf(fmaf(S[nb][0], ATTN_SCALE, -2.0f)) : 0.0f;
            float p01 = ok01 ? __expf(fmaf(S[nb][1], ATTN_SCALE, -2.0f)) : 0.0f;
            float p10 = ok10 ? __expf(fmaf(S[nb][2], ATTN_SCALE, -2.0f)) : 0.0f;
            float p11 = ok11 ? __expf(fmaf(S[nb][3], ATTN_SCALE, -2.0f)) : 0.0f;
            uint32_t plo = pack_f16x2(p00, p01);
            uint32_t phi = pack_f16x2(p10, p11);
            aPlo[nb] = plo;
            aPhi[nb] = phi;
            float2 rlo = __half22float2(*(__half2*)&plo);
            float2 rhi = __half22float2(*(__half2*)&phi);
            sAcc0 += rlo.x + rlo.y;
            sAcc1 += rhi.x + rhi.y;
        }

#pragma unroll
        for (int ks = 0; ks < 4; ++ks) {
            uint32_t aP[4] = {aPlo[2 * ks], aPhi[2 * ks], aPlo[2 * ks + 1], aPhi[2 * ks + 1]};
            uint32_t vAddr = vb + (uint32_t)(ks * 16 + (lane & 7) + (((lane >> 3) & 1) << 3)) * 272
                           + ((lane >> 4) << 4);
#pragma unroll
            for (int gv = 0; gv < 8; ++gv) {
                uint32_t vf[4];
                ldsm4t(vf, vAddr + gv * 32);
                mma_f16(O[gv * 2 + 0], aP, vf + 0);
                mma_f16(O[gv * 2 + 1], aP, vf + 2);
            }
        }
        __syncthreads();
    }

    sAcc0 += __shfl_xor_sync(0xffffffffu, sAcc0, 1);
    sAcc0 += __shfl_xor_sync(0xffffffffu, sAcc0, 2);
    sAcc1 += __shfl_xor_sync(0xffffffffu, sAcc1, 1);
    sAcc1 += __shfl_xor_sync(0xffffffffu, sAcc1, 2);
    float inv0 = 1.0f / sAcc0;
    float inv1 = 1.0f / sAcc1;

    float* out0 = g_ctx + ((size_t)(b * L_ + r_lo)) * E_ + h * D_;
    float* out1 = g_ctx + ((size_t)(b * L_ + r_hi)) * E_ + h * D_;
#pragma unroll
    for (int nb = 0; nb < 16; ++nb) {
        int col = nb * 8 + ((lane & 3) << 1);
        *(float2*)(out0 + col) = make_float2(O[nb][0] * inv0, O[nb][1] * inv0);
        *(float2*)(out1 + col) = make_float2(O[nb][2] * inv1, O[nb][3] * inv1);
    }
}

// ---------------------------------------------------------------------------
extern "C" void kernel_launch(void* const* d_in, const int* in_sizes, int n_in,
                              void* d_out, int out_size) {
    const float* query = (const float*)d_in[0];
    const float* key_  = (const float*)d_in[1];
    const float* value = (const float*)d_in[2];
    const float* Wq = (const float*)d_in[3];
    const float* bq = (const float*)d_in[4];
    const float* Wk = (const float*)d_in[5];
    const float* bk = (const float*)d_in[6];
    const float* Wv = (const float*)d_in[7];
    const float* bv = (const float*)d_in[8];
    const float* Wo = (const float*)d_in[9];
    const float* bo = (const float*)d_in[10];
    float* out = (float*)d_out;

    float* Cd;
    __half *Qhd, *Khd, *Vhd;
    cudaGetSymbolAddress((void**)&Qhd, g_Qh);
    cudaGetSymbolAddress((void**)&Khd, g_Kh);
    cudaGetSymbolAddress((void**)&Vhd, g_Vh);
    cudaGetSymbolAddress((void**)&Cd, g_ctx);

    dim3 ggrid(E_ / 128, (B_ * L_) / 128);   // 8 x 32 = 256 CTAs

    gemm_tf32_kernel<<<ggrid, 256>>>(query, Wq, bq, Qhd);
    gemm_tf32_kernel<<<ggrid, 256>>>(key_,  Wk, bk, Khd);
    gemm_tf32_kernel<<<ggrid, 256>>>(value, Wv, bv, Vhd);

    attn_mma_kernel<<<B_ * H_ * (L_ / 64), 128>>>();   // 512 CTAs

    gemm_tc_kernel<<<ggrid, 256>>>(Cd, Wo, bo, out);
}

// round 13
// speedup vs baseline: 1.6861x; 1.1043x over previous
#include <cuda_runtime.h>
#include <cuda_fp16.h>
#include <cstdint>
#include <math.h>

#define B_ 2
#define L_ 2048
#define E_ 1024
#define H_ 8
#define D_ 128

// Scratch (allocation-free rule: __device__ globals)
__device__ __half g_Qh[B_ * L_ * E_];
__device__ __half g_Kh[B_ * L_ * E_];
__device__ __half g_Vh[B_ * L_ * E_];
__device__ float  g_ctx[B_ * L_ * E_];

__constant__ int c_anchors[10] = {204, 409, 614, 781, 1023, 1265, 1432, 1637, 1842, 2047};

// ===========================================================================
// helpers
// ===========================================================================
__device__ __forceinline__ uint32_t smem_u32(const void* p) {
    uint32_t a;
    asm("{ .reg .u64 t; cvta.to.shared.u64 t, %1; cvt.u32.u64 %0, t; }" : "=r"(a) : "l"(p));
    return a;
}

__device__ __forceinline__ uint32_t pack_bf16x2(float x0, float x1) {
    uint32_t r;
    asm("cvt.rn.bf16x2.f32 %0, %2, %1;" : "=r"(r) : "f"(x0), "f"(x1));
    return r;
}

__device__ __forceinline__ uint32_t pack_f16x2(float x0, float x1) {
    uint32_t r;
    asm("cvt.rn.f16x2.f32 %0, %2, %1;" : "=r"(r) : "f"(x0), "f"(x1));
    return r;
}

__device__ __forceinline__ void ldsm4(uint32_t* r, uint32_t addr) {
    asm volatile("ldmatrix.sync.aligned.m8n8.x4.shared.b16 {%0,%1,%2,%3}, [%4];"
                 : "=r"(r[0]), "=r"(r[1]), "=r"(r[2]), "=r"(r[3]) : "r"(addr));
}

__device__ __forceinline__ void ldsm4t(uint32_t* r, uint32_t addr) {
    asm volatile("ldmatrix.sync.aligned.m8n8.x4.trans.shared.b16 {%0,%1,%2,%3}, [%4];"
                 : "=r"(r[0]), "=r"(r[1]), "=r"(r[2]), "=r"(r[3]) : "r"(addr));
}

__device__ __forceinline__ void mma_bf16(float* d, const uint32_t* a, const uint32_t* b) {
    asm volatile(
        "mma.sync.aligned.m16n8k16.row.col.f32.bf16.bf16.f32 "
        "{%0,%1,%2,%3}, {%4,%5,%6,%7}, {%8,%9}, {%0,%1,%2,%3};"
        : "+f"(d[0]), "+f"(d[1]), "+f"(d[2]), "+f"(d[3])
        : "r"(a[0]), "r"(a[1]), "r"(a[2]), "r"(a[3]), "r"(b[0]), "r"(b[1]));
}

__device__ __forceinline__ void mma_f16(float* d, const uint32_t* a, const uint32_t* b) {
    asm volatile(
        "mma.sync.aligned.m16n8k16.row.col.f32.f16.f16.f32 "
        "{%0,%1,%2,%3}, {%4,%5,%6,%7}, {%8,%9}, {%0,%1,%2,%3};"
        : "+f"(d[0]), "+f"(d[1]), "+f"(d[2]), "+f"(d[3])
        : "r"(a[0]), "r"(a[1]), "r"(a[2]), "r"(a[3]), "r"(b[0]), "r"(b[1]));
}

#define CP16(dst, src) \
    asm volatile("cp.async.cg.shared.global [%0], [%1], 16;" :: "r"(dst), "l"(src) : "memory")

// ===========================================================================
// Single-pass FP16 GEMM (fp16 u = 2^-11 = tf32 u, but 2x MACs/instr + ldmatrix):
//   C = A @ W^T + bias, half output.  For Q/K/V projections.
// CTA 128x128, 8 warps (2m x 4n), warp tile 64x32, BK=32.
// Same validated LDA=80 padded layout / frag addressing as the split kernel.
// ===========================================================================
#define LDA 80
#define T_BYTES (128 * LDA)

__global__ __launch_bounds__(256, 1)
void gemm_f16_kernel(const float* __restrict__ A, const float* __restrict__ W,
                     const float* __restrict__ bias, __half* __restrict__ Cout) {
    __shared__ __align__(16) uint8_t smA[T_BYTES];
    __shared__ __align__(16) uint8_t smW[T_BYTES];
    uint32_t sbA = smem_u32(smA);
    uint32_t sbW = smem_u32(smW);

    int tid = threadIdx.x;
    int lane = tid & 31;
    int wid = tid >> 5;
    int warpM = wid >> 2;
    int warpN = wid & 3;

    const float* Ag = A + (size_t)blockIdx.y * 128 * 1024;
    const float* Wg = W + (size_t)blockIdx.x * 128 * 1024;

    int r0 = tid >> 3;
    int c4 = tid & 7;

    float4 pa[4], pw[4];
#pragma unroll
    for (int i = 0; i < 4; ++i) {
        pa[i] = *(const float4*)(Ag + (size_t)(r0 + i * 32) * 1024 + c4 * 4);
        pw[i] = *(const float4*)(Wg + (size_t)(r0 + i * 32) * 1024 + c4 * 4);
    }

    float acc[4][4][4];
#pragma unroll
    for (int f = 0; f < 4; ++f)
#pragma unroll
        for (int g = 0; g < 4; ++g)
#pragma unroll
            for (int r = 0; r < 4; ++r) acc[f][g][r] = 0.0f;

    uint32_t aRow = (uint32_t)(warpM * 64) + (lane & 15);
    uint32_t aAddrBase = aRow * LDA + ((lane >> 4) << 4);
    uint32_t bRow = (uint32_t)(warpN * 32) + (lane & 7) + ((lane >> 4) << 3);
    uint32_t bAddrBase = bRow * LDA + (((lane >> 3) & 1) << 4);

    for (int kt = 0; kt < 32; ++kt) {
#pragma unroll
        for (int i = 0; i < 4; ++i) {
            uint32_t so = (uint32_t)(r0 + i * 32) * LDA + c4 * 8;
            float4 v = pa[i];
            *(uint2*)(smA + so) = make_uint2(pack_f16x2(v.x, v.y), pack_f16x2(v.z, v.w));
            v = pw[i];
            *(uint2*)(smW + so) = make_uint2(pack_f16x2(v.x, v.y), pack_f16x2(v.z, v.w));
        }
        __syncthreads();

        if (kt < 31) {
            int k0 = (kt + 1) * 32;
#pragma unroll
            for (int i = 0; i < 4; ++i) {
                pa[i] = *(const float4*)(Ag + (size_t)(r0 + i * 32) * 1024 + k0 + c4 * 4);
                pw[i] = *(const float4*)(Wg + (size_t)(r0 + i * 32) * 1024 + k0 + c4 * 4);
            }
        }

#pragma unroll
        for (int ks = 0; ks < 2; ++ks) {
            uint32_t koff = ks * 32;
            uint32_t bF[2][4];
            ldsm4(bF[0], sbW + bAddrBase + koff);
            ldsm4(bF[1], sbW + bAddrBase + 16 * LDA + koff);
#pragma unroll
            for (int f = 0; f < 4; ++f) {
                uint32_t aF[4];
                ldsm4(aF, sbA + aAddrBase + (uint32_t)(f * 16) * LDA + koff);
#pragma unroll
                for (int g = 0; g < 4; ++g)
                    mma_f16(acc[f][g], aF, &bF[g >> 1][(g & 1) * 2]);
            }
        }
        __syncthreads();
    }

    int crow = blockIdx.y * 128 + warpM * 64 + (lane >> 2);
    int ccol0 = blockIdx.x * 128 + warpN * 32 + (lane & 3) * 2;
#pragma unroll
    for (int g = 0; g < 4; ++g) {
        int c = ccol0 + g * 8;
        float2 bv = *(const float2*)(bias + c);
#pragma unroll
        for (int f = 0; f < 4; ++f) {
            int r = crow + f * 16;
            *(__half2*)(Cout + (size_t)r * 1024 + c) =
                __floats2half2_rn(acc[f][g][0] + bv.x, acc[f][g][1] + bv.y);
            *(__half2*)(Cout + (size_t)(r + 8) * 1024 + c) =
                __floats2half2_rn(acc[f][g][2] + bv.x, acc[f][g][3] + bv.y);
        }
    }
}

// ===========================================================================
// Split-bf16 GEMM (hi/lo, 3 mma) — Wo projection only (full precision)
// ===========================================================================
#define AH_OFF 0
#define AL_OFF (T_BYTES)
#define WH_OFF (2 * T_BYTES)
#define WL_OFF (3 * T_BYTES)

__global__ __launch_bounds__(256, 1)
void gemm_tc_kernel(const float* __restrict__ A, const float* __restrict__ W,
                    const float* __restrict__ bias, float* __restrict__ Cout) {
    __shared__ __align__(16) uint8_t sm[4 * T_BYTES];
    uint32_t sb = smem_u32(sm);

    int tid = threadIdx.x;
    int lane = tid & 31;
    int wid = tid >> 5;
    int warpM = wid >> 2;
    int warpN = wid & 3;

    const float* Ag = A + (size_t)blockIdx.y * 128 * 1024;
    const float* Wg = W + (size_t)blockIdx.x * 128 * 1024;

    int r0 = tid >> 3;
    int c4 = tid & 7;

    float4 pa[4], pw[4];
#pragma unroll
    for (int i = 0; i < 4; ++i) {
        pa[i] = *(const float4*)(Ag + (size_t)(r0 + i * 32) * 1024 + c4 * 4);
        pw[i] = *(const float4*)(Wg + (size_t)(r0 + i * 32) * 1024 + c4 * 4);
    }

    float acc[4][4][4];
#pragma unroll
    for (int f = 0; f < 4; ++f)
#pragma unroll
        for (int g = 0; g < 4; ++g)
#pragma unroll
            for (int r = 0; r < 4; ++r) acc[f][g][r] = 0.0f;

    uint32_t aRow = (uint32_t)(warpM * 64) + (lane & 15);
    uint32_t aAddrBase = aRow * LDA + ((lane >> 4) << 4);
    uint32_t bRow = (uint32_t)(warpN * 32) + (lane & 7) + ((lane >> 4) << 3);
    uint32_t bAddrBase = bRow * LDA + (((lane >> 3) & 1) << 4);

    for (int kt = 0; kt < 32; ++kt) {
#pragma unroll
        for (int i = 0; i < 4; ++i) {
            uint32_t so = (uint32_t)(r0 + i * 32) * LDA + c4 * 8;
            float4 v = pa[i];
            uint32_t h0 = pack_bf16x2(v.x, v.y);
            uint32_t h1 = pack_bf16x2(v.z, v.w);
            float l0 = v.x - __uint_as_float(h0 << 16);
            float l1 = v.y - __uint_as_float(h0 & 0xFFFF0000u);
            float l2 = v.z - __uint_as_float(h1 << 16);
            float l3 = v.w - __uint_as_float(h1 & 0xFFFF0000u);
            *(uint2*)(sm + AH_OFF + so) = make_uint2(h0, h1);
            *(uint2*)(sm + AL_OFF + so) = make_uint2(pack_bf16x2(l0, l1), pack_bf16x2(l2, l3));
            v = pw[i];
            h0 = pack_bf16x2(v.x, v.y);
            h1 = pack_bf16x2(v.z, v.w);
            l0 = v.x - __uint_as_float(h0 << 16);
            l1 = v.y - __uint_as_float(h0 & 0xFFFF0000u);
            l2 = v.z - __uint_as_float(h1 << 16);
            l3 = v.w - __uint_as_float(h1 & 0xFFFF0000u);
            *(uint2*)(sm + WH_OFF + so) = make_uint2(h0, h1);
            *(uint2*)(sm + WL_OFF + so) = make_uint2(pack_bf16x2(l0, l1), pack_bf16x2(l2, l3));
        }
        __syncthreads();

        if (kt < 31) {
            int k0 = (kt + 1) * 32;
#pragma unroll
            for (int i = 0; i < 4; ++i) {
                pa[i] = *(const float4*)(Ag + (size_t)(r0 + i * 32) * 1024 + k0 + c4 * 4);
                pw[i] = *(const float4*)(Wg + (size_t)(r0 + i * 32) * 1024 + k0 + c4 * 4);
            }
        }

#pragma unroll
        for (int ks = 0; ks < 2; ++ks) {
            uint32_t koff = ks * 32;
            uint32_t bH[2][4], bL[2][4];
            ldsm4(bH[0], sb + WH_OFF + bAddrBase + koff);
            ldsm4(bH[1], sb + WH_OFF + bAddrBase + 16 * LDA + koff);
            ldsm4(bL[0], sb + WL_OFF + bAddrBase + koff);
            ldsm4(bL[1], sb + WL_OFF + bAddrBase + 16 * LDA + koff);
#pragma unroll
            for (int f = 0; f < 4; ++f) {
                uint32_t aH[4], aL[4];
                ldsm4(aH, sb + AH_OFF + aAddrBase + (uint32_t)(f * 16) * LDA + koff);
                ldsm4(aL, sb + AL_OFF + aAddrBase + (uint32_t)(f * 16) * LDA + koff);
#pragma unroll
                for (int g = 0; g < 4; ++g) {
                    const uint32_t* bh = &bH[g >> 1][(g & 1) * 2];
                    const uint32_t* bl = &bL[g >> 1][(g & 1) * 2];
                    mma_bf16(acc[f][g], aH, bh);
                    mma_bf16(acc[f][g], aL, bh);
                    mma_bf16(acc[f][g], aH, bl);
                }
            }
        }
        __syncthreads();
    }

    int crow = blockIdx.y * 128 + warpM * 64 + (lane >> 2);
    int ccol0 = blockIdx.x * 128 + warpN * 32 + (lane & 3) * 2;
#pragma unroll
    for (int g = 0; g < 4; ++g) {
        int c = ccol0 + g * 8;
        float2 bv = *(const float2*)(bias + c);
#pragma unroll
        for (int f = 0; f < 4; ++f) {
            int r = crow + f * 16;
            *(float2*)(Cout + (size_t)r * 1024 + c) =
                make_float2(acc[f][g][0] + bv.x, acc[f][g][1] + bv.y);
            *(float2*)(Cout + (size_t)(r + 8) * 1024 + c) =
                make_float2(acc[f][g][2] + bv.x, acc[f][g][3] + bv.y);
        }
    }
}

// ===========================================================================
// MMA sparse attention (R9/R11, passing — unchanged)
// ===========================================================================
#define LDKV 136
#define MAXCOLS 384
#define ATTN_SCALE 0.08838834764831845f

__global__ __launch_bounds__(128, 1)
void attn_mma_kernel() {
    __shared__ int colsSm[MAXCOLS];
    __shared__ __align__(16) __half Ksm[64 * LDKV];
    __shared__ __align__(16) __half Vsm[64 * LDKV];

    int tid = threadIdx.x;
    int lane = tid & 31;
    int w = tid >> 5;

    int bid = blockIdx.x;
    int tile = 31 - (bid >> 4);
    int h = bid & 7;
    int b = (bid >> 3) & 1;
    int i0 = tile * 64;
    int cl = (h == 0) ? 0 : (h <= 2) ? 3 : (h <= 5) ? 1 : 2;

    int ncol;
    if (cl == 2) {
        int n16 = ((i0 + 63) >> 4) + 1;
        for (int t = tid; t < n16; t += 128) colsSm[t] = t << 4;
        if (tid < 10) colsSm[n16 + tid] = c_anchors[tid];
        ncol = n16 + 10;
    } else {
        int wr = (cl == 0) ? 8 : (cl == 3) ? 16 : 32;
        int wstart = i0 - wr; if (wstart < 0) wstart = 0;
        int ns = (cl == 1) ? ((wstart + 7) >> 3) : 0;
        int nw = i0 + 63 - wstart + 1;
        if (cl == 1)
            for (int t = tid; t < ns; t += 128) colsSm[t] = t << 3;
        for (int t = tid; t < nw; t += 128) colsSm[ns + t] = wstart + t;
        ncol = ns + nw;
    }
    int npad = (ncol + 63) & ~63;
    for (int t = ncol + tid; t < npad; t += 128) colsSm[t] = 1 << 28;

    {
        int m = tid >> 1;
        int hf = tid & 1;
        const uint4* src = (const uint4*)(g_Qh + ((size_t)(b * L_ + i0 + m)) * E_ + h * D_ + hf * 64);
        uint4* dst = (uint4*)(Ksm + m * LDKV + hf * 64);
#pragma unroll
        for (int t = 0; t < 8; ++t) dst[t] = src[t];
    }
    __syncthreads();

    uint32_t kb = smem_u32(Ksm);
    uint32_t vb = smem_u32(Vsm);

    uint32_t qf[8][4];
    {
        uint32_t aAddr = kb + (uint32_t)(w * 16 + (lane & 15)) * 272 + ((lane >> 4) << 4);
#pragma unroll
        for (int ks = 0; ks < 8; ++ks)
            ldsm4(qf[ks], aAddr + ks * 32);
    }
    __syncthreads();

    float O[16][4];
#pragma unroll
    for (int nb = 0; nb < 16; ++nb)
#pragma unroll
        for (int r = 0; r < 4; ++r) O[nb][r] = 0.0f;
    float sAcc0 = 0.0f, sAcc1 = 0.0f;

    int r_lo = i0 + w * 16 + (lane >> 2);
    int r_hi = r_lo + 8;

    int nchunks = npad >> 6;
    for (int ci = 0; ci < nchunks; ++ci) {
        {
            int slot = tid >> 1;
            int hf = tid & 1;
            int j = colsSm[ci * 64 + slot];
            int jg = (j < L_) ? j : 0;
            size_t go = ((size_t)(b * L_ + jg)) * E_ + h * D_ + hf * 64;
            uint32_t dK = kb + (uint32_t)slot * 272 + hf * 128;
            uint32_t dV = vb + (uint32_t)slot * 272 + hf * 128;
            const __half* sK = g_Kh + go;
            const __half* sV = g_Vh + go;
#pragma unroll
            for (int t = 0; t < 8; ++t) {
                CP16(dK + t * 16, sK + t * 8);
                CP16(dV + t * 16, sV + t * 8);
            }
            asm volatile("cp.async.commit_group;" ::: "memory");
            asm volatile("cp.async.wait_group 0;" ::: "memory");
        }
        __syncthreads();

        float S[8][4];
#pragma unroll
        for (int nb = 0; nb < 8; ++nb)
#pragma unroll
            for (int r = 0; r < 4; ++r) S[nb][r] = 0.0f;

        uint32_t bBase = kb + (uint32_t)((lane & 7) + ((lane >> 4) << 3)) * 272 + (((lane >> 3) & 1) << 4);
#pragma unroll
        for (int g2 = 0; g2 < 4; ++g2) {
#pragma unroll
            for (int ks = 0; ks < 8; ++ks) {
                uint32_t bf[4];
                ldsm4(bf, bBase + (uint32_t)(g2 * 16) * 272 + ks * 32);
                mma_f16(S[g2 * 2 + 0], qf[ks], bf + 0);
                mma_f16(S[g2 * 2 + 1], qf[ks], bf + 2);
            }
        }

        uint32_t aPlo[8], aPhi[8];
#pragma unroll
        for (int nb = 0; nb < 8; ++nb) {
            int cidx = ci * 64 + nb * 8 + ((lane & 3) << 1);
            int j0 = colsSm[cidx];
            int j1 = colsSm[cidx + 1];
            bool ok00, ok01, ok10, ok11;
            if (cl == 0) {
                ok00 = (j0 <= r_lo) && (r_lo - j0 <= 8);
                ok01 = (j1 <= r_lo) && (r_lo - j1 <= 8);
                ok10 = (j0 <= r_hi) && (r_hi - j0 <= 8);
                ok11 = (j1 <= r_hi) && (r_hi - j1 <= 8);
            } else if (cl == 3) {
                ok00 = (j0 <= r_lo) && (r_lo - j0 <= 16);
                ok01 = (j1 <= r_lo) && (r_lo - j1 <= 16);
                ok10 = (j0 <= r_hi) && (r_hi - j0 <= 16);
                ok11 = (j1 <= r_hi) && (r_hi - j1 <= 16);
            } else if (cl == 1) {
                ok00 = (j0 <= r_lo) && ((r_lo - j0 <= 32) || ((j0 & 7) == 0));
                ok01 = (j1 <= r_lo) && ((r_lo - j1 <= 32) || ((j1 & 7) == 0));
                ok10 = (j0 <= r_hi) && ((r_hi - j0 <= 32) || ((j0 & 7) == 0));
                ok11 = (j1 <= r_hi) && ((r_hi - j1 <= 32) || ((j1 & 7) == 0));
            } else {
                ok00 = (j0 <= r_lo);
                ok01 = (j1 <= r_lo);
                ok10 = (j0 <= r_hi);
                ok11 = (j1 <= r_hi);
            }
            float p00 = ok00 ? __expf(fmaf(S[nb][0], ATTN_SCALE, -2.0f)) : 0.0f;
            float p01 = ok01 ? __expf(fmaf(S[nb][1], ATTN_SCALE, -2.0f)) : 0.0f;
            float p10 = ok10 ? __expf(fmaf(S[nb][2], ATTN_SCALE, -2.0f)) : 0.0f;
            float p11 = ok11 ? __expf(fmaf(S[nb][3], ATTN_SCALE, -2.0f)) : 0.0f;
            uint32_t plo = pack_f16x2(p00, p01);
            uint32_t phi = pack_f16x2(p10, p11);
            aPlo[nb] = plo;
            aPhi[nb] = phi;
            float2 rlo = __half22float2(*(__half2*)&plo);
            float2 rhi = __half22float2(*(__half2*)&phi);
            sAcc0 += rlo.x + rlo.y;
            sAcc1 += rhi.x + rhi.y;
        }

#pragma unroll
        for (int ks = 0; ks < 4; ++ks) {
            uint32_t aP[4] = {aPlo[2 * ks], aPhi[2 * ks], aPlo[2 * ks + 1], aPhi[2 * ks + 1]};
            uint32_t vAddr = vb + (uint32_t)(ks * 16 + (lane & 7) + (((lane >> 3) & 1) << 3)) * 272
                           + ((lane >> 4) << 4);
#pragma unroll
            for (int gv = 0; gv < 8; ++gv) {
                uint32_t vf[4];
                ldsm4t(vf, vAddr + gv * 32);
                mma_f16(O[gv * 2 + 0], aP, vf + 0);
                mma_f16(O[gv * 2 + 1], aP, vf + 2);
            }
        }
        __syncthreads();
    }

    sAcc0 += __shfl_xor_sync(0xffffffffu, sAcc0, 1);
    sAcc0 += __shfl_xor_sync(0xffffffffu, sAcc0, 2);
    sAcc1 += __shfl_xor_sync(0xffffffffu, sAcc1, 1);
    sAcc1 += __shfl_xor_sync(0xffffffffu, sAcc1, 2);
    float inv0 = 1.0f / sAcc0;
    float inv1 = 1.0f / sAcc1;

    float* out0 = g_ctx + ((size_t)(b * L_ + r_lo)) * E_ + h * D_;
    float* out1 = g_ctx + ((size_t)(b * L_ + r_hi)) * E_ + h * D_;
#pragma unroll
    for (int nb = 0; nb < 16; ++nb) {
        int col = nb * 8 + ((lane & 3) << 1);
        *(float2*)(out0 + col) = make_float2(O[nb][0] * inv0, O[nb][1] * inv0);
        *(float2*)(out1 + col) = make_float2(O[nb][2] * inv1, O[nb][3] * inv1);
    }
}

// ---------------------------------------------------------------------------
extern "C" void kernel_launch(void* const* d_in, const int* in_sizes, int n_in,
                              void* d_out, int out_size) {
    const float* query = (const float*)d_in[0];
    const float* key_  = (const float*)d_in[1];
    const float* value = (const float*)d_in[2];
    const float* Wq = (const float*)d_in[3];
    const float* bq = (const float*)d_in[4];
    const float* Wk = (const float*)d_in[5];
    const float* bk = (const float*)d_in[6];
    const float* Wv = (const float*)d_in[7];
    const float* bv = (const float*)d_in[8];
    const float* Wo = (const float*)d_in[9];
    const float* bo = (const float*)d_in[10];
    float* out = (float*)d_out;

    float* Cd;
    __half *Qhd, *Khd, *Vhd;
    cudaGetSymbolAddress((void**)&Qhd, g_Qh);
    cudaGetSymbolAddress((void**)&Khd, g_Kh);
    cudaGetSymbolAddress((void**)&Vhd, g_Vh);
    cudaGetSymbolAddress((void**)&Cd, g_ctx);

    dim3 ggrid(E_ / 128, (B_ * L_) / 128);   // 8 x 32 = 256 CTAs

    gemm_f16_kernel<<<ggrid, 256>>>(query, Wq, bq, Qhd);
    gemm_f16_kernel<<<ggrid, 256>>>(key_,  Wk, bk, Khd);
    gemm_f16_kernel<<<ggrid, 256>>>(value, Wv, bv, Vhd);

    attn_mma_kernel<<<B_ * H_ * (L_ / 64), 128>>>();   // 512 CTAs

    gemm_tc_kernel<<<ggrid, 256>>>(Cd, Wo, bo, out);
}

// round 15
// speedup vs baseline: 2.8429x; 1.6860x over previous
#include <cuda_runtime.h>
#include <cuda_fp16.h>
#include <cstdint>
#include <math.h>

#define B_ 2
#define L_ 2048
#define E_ 1024
#define H_ 8
#define D_ 128

// Scratch (allocation-free rule: __device__ globals)
__device__ __half g_Qh[B_ * L_ * E_];
__device__ __half g_Kh[B_ * L_ * E_];
__device__ __half g_Vh[B_ * L_ * E_];
__device__ float  g_ctx[B_ * L_ * E_];

__constant__ int c_anchors[10] = {204, 409, 614, 781, 1023, 1265, 1432, 1637, 1842, 2047};

// ===========================================================================
// helpers
// ===========================================================================
__device__ __forceinline__ uint32_t smem_u32(const void* p) {
    uint32_t a;
    asm("{ .reg .u64 t; cvta.to.shared.u64 t, %1; cvt.u32.u64 %0, t; }" : "=r"(a) : "l"(p));
    return a;
}

__device__ __forceinline__ uint32_t pack_f16x2(float x0, float x1) {
    uint32_t r;
    asm("cvt.rn.f16x2.f32 %0, %2, %1;" : "=r"(r) : "f"(x0), "f"(x1));
    return r;
}

__device__ __forceinline__ void ldsm4(uint32_t* r, uint32_t addr) {
    asm volatile("ldmatrix.sync.aligned.m8n8.x4.shared.b16 {%0,%1,%2,%3}, [%4];"
                 : "=r"(r[0]), "=r"(r[1]), "=r"(r[2]), "=r"(r[3]) : "r"(addr));
}

__device__ __forceinline__ void ldsm4t(uint32_t* r, uint32_t addr) {
    asm volatile("ldmatrix.sync.aligned.m8n8.x4.trans.shared.b16 {%0,%1,%2,%3}, [%4];"
                 : "=r"(r[0]), "=r"(r[1]), "=r"(r[2]), "=r"(r[3]) : "r"(addr));
}

__device__ __forceinline__ void mma_f16(float* d, const uint32_t* a, const uint32_t* b) {
    asm volatile(
        "mma.sync.aligned.m16n8k16.row.col.f32.f16.f16.f32 "
        "{%0,%1,%2,%3}, {%4,%5,%6,%7}, {%8,%9}, {%0,%1,%2,%3};"
        : "+f"(d[0]), "+f"(d[1]), "+f"(d[2]), "+f"(d[3])
        : "r"(a[0]), "r"(a[1]), "r"(a[2]), "r"(a[3]), "r"(b[0]), "r"(b[1]));
}

#define CP16(dst, src) \
    asm volatile("cp.async.cg.shared.global [%0], [%1], 16;" :: "r"(dst), "l"(src) : "memory")

// ===========================================================================
// Single-pass FP16 GEMM, occupancy 2:  C = A @ W^T + bias
// Templated output type: __half for Q/K/V, float for the Wo projection.
// CTA 128x128, 8 warps (2m x 4n), warp tile 64x32, BK=32, LDA=80 padded.
// ===========================================================================
#define LDA 80
#define T_BYTES (128 * LDA)

template <typename OutT>
__global__ __launch_bounds__(256, 2)
void gemm_f16_kernel(const float* __restrict__ A, const float* __restrict__ W,
                     const float* __restrict__ bias, OutT* __restrict__ Cout) {
    __shared__ __align__(16) uint8_t smA[T_BYTES];
    __shared__ __align__(16) uint8_t smW[T_BYTES];
    uint32_t sbA = smem_u32(smA);
    uint32_t sbW = smem_u32(smW);

    int tid = threadIdx.x;
    int lane = tid & 31;
    int wid = tid >> 5;
    int warpM = wid >> 2;
    int warpN = wid & 3;

    const float* Ag = A + (size_t)blockIdx.y * 128 * 1024;
    const float* Wg = W + (size_t)blockIdx.x * 128 * 1024;

    int r0 = tid >> 3;
    int c4 = tid & 7;

    float4 pa[4], pw[4];
#pragma unroll
    for (int i = 0; i < 4; ++i) {
        pa[i] = *(const float4*)(Ag + (size_t)(r0 + i * 32) * 1024 + c4 * 4);
        pw[i] = *(const float4*)(Wg + (size_t)(r0 + i * 32) * 1024 + c4 * 4);
    }

    float acc[4][4][4];
#pragma unroll
    for (int f = 0; f < 4; ++f)
#pragma unroll
        for (int g = 0; g < 4; ++g)
#pragma unroll
            for (int r = 0; r < 4; ++r) acc[f][g][r] = 0.0f;

    uint32_t aRow = (uint32_t)(warpM * 64) + (lane & 15);
    uint32_t aAddrBase = aRow * LDA + ((lane >> 4) << 4);
    uint32_t bRow = (uint32_t)(warpN * 32) + (lane & 7) + ((lane >> 4) << 3);
    uint32_t bAddrBase = bRow * LDA + (((lane >> 3) & 1) << 4);

    for (int kt = 0; kt < 32; ++kt) {
#pragma unroll
        for (int i = 0; i < 4; ++i) {
            uint32_t so = (uint32_t)(r0 + i * 32) * LDA + c4 * 8;
            float4 v = pa[i];
            *(uint2*)(smA + so) = make_uint2(pack_f16x2(v.x, v.y), pack_f16x2(v.z, v.w));
            v = pw[i];
            *(uint2*)(smW + so) = make_uint2(pack_f16x2(v.x, v.y), pack_f16x2(v.z, v.w));
        }
        __syncthreads();

        if (kt < 31) {
            int k0 = (kt + 1) * 32;
#pragma unroll
            for (int i = 0; i < 4; ++i) {
                pa[i] = *(const float4*)(Ag + (size_t)(r0 + i * 32) * 1024 + k0 + c4 * 4);
                pw[i] = *(const float4*)(Wg + (size_t)(r0 + i * 32) * 1024 + k0 + c4 * 4);
            }
        }

#pragma unroll
        for (int ks = 0; ks < 2; ++ks) {
            uint32_t koff = ks * 32;
            uint32_t bF[2][4];
            ldsm4(bF[0], sbW + bAddrBase + koff);
            ldsm4(bF[1], sbW + bAddrBase + 16 * LDA + koff);
#pragma unroll
            for (int f = 0; f < 4; ++f) {
                uint32_t aF[4];
                ldsm4(aF, sbA + aAddrBase + (uint32_t)(f * 16) * LDA + koff);
#pragma unroll
                for (int g = 0; g < 4; ++g)
                    mma_f16(acc[f][g], aF, &bF[g >> 1][(g & 1) * 2]);
            }
        }
        __syncthreads();
    }

    int crow = blockIdx.y * 128 + warpM * 64 + (lane >> 2);
    int ccol0 = blockIdx.x * 128 + warpN * 32 + (lane & 3) * 2;
#pragma unroll
    for (int g = 0; g < 4; ++g) {
        int c = ccol0 + g * 8;
        float2 bv = *(const float2*)(bias + c);
#pragma unroll
        for (int f = 0; f < 4; ++f) {
            int r = crow + f * 16;
            float o00 = acc[f][g][0] + bv.x, o01 = acc[f][g][1] + bv.y;
            float o10 = acc[f][g][2] + bv.x, o11 = acc[f][g][3] + bv.y;
            if (sizeof(OutT) == 2) {
                __half* Ch = (__half*)Cout;
                *(__half2*)(Ch + (size_t)r * 1024 + c) = __floats2half2_rn(o00, o01);
                *(__half2*)(Ch + (size_t)(r + 8) * 1024 + c) = __floats2half2_rn(o10, o11);
            } else {
                float* Cf = (float*)Cout;
                *(float2*)(Cf + (size_t)r * 1024 + c) = make_float2(o00, o01);
                *(float2*)(Cf + (size_t)(r + 8) * 1024 + c) = make_float2(o10, o11);
            }
        }
    }
}

// ===========================================================================
// MMA sparse attention (R9/R11/R13, passing — unchanged)
// ===========================================================================
#define LDKV 136
#define MAXCOLS 384
#define ATTN_SCALE 0.08838834764831845f

__global__ __launch_bounds__(128, 1)
void attn_mma_kernel() {
    __shared__ int colsSm[MAXCOLS];
    __shared__ __align__(16) __half Ksm[64 * LDKV];
    __shared__ __align__(16) __half Vsm[64 * LDKV];

    int tid = threadIdx.x;
    int lane = tid & 31;
    int w = tid >> 5;

    int bid = blockIdx.x;
    int tile = 31 - (bid >> 4);
    int h = bid & 7;
    int b = (bid >> 3) & 1;
    int i0 = tile * 64;
    int cl = (h == 0) ? 0 : (h <= 2) ? 3 : (h <= 5) ? 1 : 2;

    int ncol;
    if (cl == 2) {
        int n16 = ((i0 + 63) >> 4) + 1;
        for (int t = tid; t < n16; t += 128) colsSm[t] = t << 4;
        if (tid < 10) colsSm[n16 + tid] = c_anchors[tid];
        ncol = n16 + 10;
    } else {
        int wr = (cl == 0) ? 8 : (cl == 3) ? 16 : 32;
        int wstart = i0 - wr; if (wstart < 0) wstart = 0;
        int ns = (cl == 1) ? ((wstart + 7) >> 3) : 0;
        int nw = i0 + 63 - wstart + 1;
        if (cl == 1)
            for (int t = tid; t < ns; t += 128) colsSm[t] = t << 3;
        for (int t = tid; t < nw; t += 128) colsSm[ns + t] = wstart + t;
        ncol = ns + nw;
    }
    int npad = (ncol + 63) & ~63;
    for (int t = ncol + tid; t < npad; t += 128) colsSm[t] = 1 << 28;

    {
        int m = tid >> 1;
        int hf = tid & 1;
        const uint4* src = (const uint4*)(g_Qh + ((size_t)(b * L_ + i0 + m)) * E_ + h * D_ + hf * 64);
        uint4* dst = (uint4*)(Ksm + m * LDKV + hf * 64);
#pragma unroll
        for (int t = 0; t < 8; ++t) dst[t] = src[t];
    }
    __syncthreads();

    uint32_t kb = smem_u32(Ksm);
    uint32_t vb = smem_u32(Vsm);

    uint32_t qf[8][4];
    {
        uint32_t aAddr = kb + (uint32_t)(w * 16 + (lane & 15)) * 272 + ((lane >> 4) << 4);
#pragma unroll
        for (int ks = 0; ks < 8; ++ks)
            ldsm4(qf[ks], aAddr + ks * 32);
    }
    __syncthreads();

    float O[16][4];
#pragma unroll
    for (int nb = 0; nb < 16; ++nb)
#pragma unroll
        for (int r = 0; r < 4; ++r) O[nb][r] = 0.0f;
    float sAcc0 = 0.0f, sAcc1 = 0.0f;

    int r_lo = i0 + w * 16 + (lane >> 2);
    int r_hi = r_lo + 8;

    int nchunks = npad >> 6;
    for (int ci = 0; ci < nchunks; ++ci) {
        {
            int slot = tid >> 1;
            int hf = tid & 1;
            int j = colsSm[ci * 64 + slot];
            int jg = (j < L_) ? j : 0;
            size_t go = ((size_t)(b * L_ + jg)) * E_ + h * D_ + hf * 64;
            uint32_t dK = kb + (uint32_t)slot * 272 + hf * 128;
            uint32_t dV = vb + (uint32_t)slot * 272 + hf * 128;
            const __half* sK = g_Kh + go;
            const __half* sV = g_Vh + go;
#pragma unroll
            for (int t = 0; t < 8; ++t) {
                CP16(dK + t * 16, sK + t * 8);
                CP16(dV + t * 16, sV + t * 8);
            }
            asm volatile("cp.async.commit_group;" ::: "memory");
            asm volatile("cp.async.wait_group 0;" ::: "memory");
        }
        __syncthreads();

        float S[8][4];
#pragma unroll
        for (int nb = 0; nb < 8; ++nb)
#pragma unroll
            for (int r = 0; r < 4; ++r) S[nb][r] = 0.0f;

        uint32_t bBase = kb + (uint32_t)((lane & 7) + ((lane >> 4) << 3)) * 272 + (((lane >> 3) & 1) << 4);
#pragma unroll
        for (int g2 = 0; g2 < 4; ++g2) {
#pragma unroll
            for (int ks = 0; ks < 8; ++ks) {
                uint32_t bf[4];
                ldsm4(bf, bBase + (uint32_t)(g2 * 16) * 272 + ks * 32);
                mma_f16(S[g2 * 2 + 0], qf[ks], bf + 0);
                mma_f16(S[g2 * 2 + 1], qf[ks], bf + 2);
            }
        }

        uint32_t aPlo[8], aPhi[8];
#pragma unroll
        for (int nb = 0; nb < 8; ++nb) {
            int cidx = ci * 64 + nb * 8 + ((lane & 3) << 1);
            int j0 = colsSm[cidx];
            int j1 = colsSm[cidx + 1];
            bool ok00, ok01, ok10, ok11;
            if (cl == 0) {
                ok00 = (j0 <= r_lo) && (r_lo - j0 <= 8);
                ok01 = (j1 <= r_lo) && (r_lo - j1 <= 8);
                ok10 = (j0 <= r_hi) && (r_hi - j0 <= 8);
                ok11 = (j1 <= r_hi) && (r_hi - j1 <= 8);
            } else if (cl == 3) {
                ok00 = (j0 <= r_lo) && (r_lo - j0 <= 16);
                ok01 = (j1 <= r_lo) && (r_lo - j1 <= 16);
                ok10 = (j0 <= r_hi) && (r_hi - j0 <= 16);
                ok11 = (j1 <= r_hi) && (r_hi - j1 <= 16);
            } else if (cl == 1) {
                ok00 = (j0 <= r_lo) && ((r_lo - j0 <= 32) || ((j0 & 7) == 0));
                ok01 = (j1 <= r_lo) && ((r_lo - j1 <= 32) || ((j1 & 7) == 0));
                ok10 = (j0 <= r_hi) && ((r_hi - j0 <= 32) || ((j0 & 7) == 0));
                ok11 = (j1 <= r_hi) && ((r_hi - j1 <= 32) || ((j1 & 7) == 0));
            } else {
                ok00 = (j0 <= r_lo);
                ok01 = (j1 <= r_lo);
                ok10 = (j0 <= r_hi);
                ok11 = (j1 <= r_hi);
            }
            float p00 = ok00 ? __expf(fmaf(S[nb][0], ATTN_SCALE, -2.0f)) : 0.0f;
            float p01 = ok01 ? __expf(fmaf(S[nb][1], ATTN_SCALE, -2.0f)) : 0.0f;
            float p10 = ok10 ? __expf(fmaf(S[nb][2], ATTN_SCALE, -2.0f)) : 0.0f;
            float p11 = ok11 ? __expf(fmaf(S[nb][3], ATTN_SCALE, -2.0f)) : 0.0f;
            uint32_t plo = pack_f16x2(p00, p01);
            uint32_t phi = pack_f16x2(p10, p11);
            aPlo[nb] = plo;
            aPhi[nb] = phi;
            float2 rlo = __half22float2(*(__half2*)&plo);
            float2 rhi = __half22float2(*(__half2*)&phi);
            sAcc0 += rlo.x + rlo.y;
            sAcc1 += rhi.x + rhi.y;
        }

#pragma unroll
        for (int ks = 0; ks < 4; ++ks) {
            uint32_t aP[4] = {aPlo[2 * ks], aPhi[2 * ks], aPlo[2 * ks + 1], aPhi[2 * ks + 1]};
            uint32_t vAddr = vb + (uint32_t)(ks * 16 + (lane & 7) + (((lane >> 3) & 1) << 3)) * 272
                           + ((lane >> 4) << 4);
#pragma unroll
            for (int gv = 0; gv < 8; ++gv) {
                uint32_t vf[4];
                ldsm4t(vf, vAddr + gv * 32);
                mma_f16(O[gv * 2 + 0], aP, vf + 0);
                mma_f16(O[gv * 2 + 1], aP, vf + 2);
            }
        }
        __syncthreads();
    }

    sAcc0 += __shfl_xor_sync(0xffffffffu, sAcc0, 1);
    sAcc0 += __shfl_xor_sync(0xffffffffu, sAcc0, 2);
    sAcc1 += __shfl_xor_sync(0xffffffffu, sAcc1, 1);
    sAcc1 += __shfl_xor_sync(0xffffffffu, sAcc1, 2);
    float inv0 = 1.0f / sAcc0;
    float inv1 = 1.0f / sAcc1;

    float* out0 = g_ctx + ((size_t)(b * L_ + r_lo)) * E_ + h * D_;
    float* out1 = g_ctx + ((size_t)(b * L_ + r_hi)) * E_ + h * D_;
#pragma unroll
    for (int nb = 0; nb < 16; ++nb) {
        int col = nb * 8 + ((lane & 3) << 1);
        *(float2*)(out0 + col) = make_float2(O[nb][0] * inv0, O[nb][1] * inv0);
        *(float2*)(out1 + col) = make_float2(O[nb][2] * inv1, O[nb][3] * inv1);
    }
}

// ---------------------------------------------------------------------------
extern "C" void kernel_launch(void* const* d_in, const int* in_sizes, int n_in,
                              void* d_out, int out_size) {
    const float* query = (const float*)d_in[0];
    const float* key_  = (const float*)d_in[1];
    const float* value = (const float*)d_in[2];
    const float* Wq = (const float*)d_in[3];
    const float* bq = (const float*)d_in[4];
    const float* Wk = (const float*)d_in[5];
    const float* bk = (const float*)d_in[6];
    const float* Wv = (const float*)d_in[7];
    const float* bv = (const float*)d_in[8];
    const float* Wo = (const float*)d_in[9];
    const float* bo = (const float*)d_in[10];
    float* out = (float*)d_out;

    float* Cd;
    __half *Qhd, *Khd, *Vhd;
    cudaGetSymbolAddress((void**)&Qhd, g_Qh);
    cudaGetSymbolAddress((void**)&Khd, g_Kh);
    cudaGetSymbolAddress((void**)&Vhd, g_Vh);
    cudaGetSymbolAddress((void**)&Cd, g_ctx);

    dim3 ggrid(E_ / 128, (B_ * L_) / 128);   // 8 x 32 = 256 CTAs

    gemm_f16_kernel<__half><<<ggrid, 256>>>(query, Wq, bq, Qhd);
    gemm_f16_kernel<__half><<<ggrid, 256>>>(key_,  Wk, bk, Khd);
    gemm_f16_kernel<__half><<<ggrid, 256>>>(value, Wv, bv, Vhd);

    attn_mma_kernel<<<B_ * H_ * (L_ / 64), 128>>>();   // 512 CTAs

    gemm_f16_kernel<float><<<ggrid, 256>>>(Cd, Wo, bo, out);
}